// round 1
// baseline (speedup 1.0000x reference)
#include <cuda_runtime.h>

#define N_    32
#define CIN   32
#define V_    500
#define T_    96
#define L_    94      // T - K + 1
#define COUT  64
#define VP    512     // padded v/w dim
#define LP    96      // padded l dim in g_xt

// Scratch (zero-initialized at module load; padding regions never written)
__device__ float g_xt  [N_ * CIN * LP * VP];        // [n][c][l][v]   ~201 MB
__device__ float g_x12 [2 * N_ * CIN * L_ * VP];    // [mat][n][c][l][w] ~394 MB
__device__ float g_Apad [VP * VP];
__device__ float g_A2pad[VP * VP];
__device__ float g_Wt  [96 * 64];                   // Wt[k][o] = w_out[o][k]

// ---------------------------------------------------------------------------
// Kernel A: Apad = zero-pad(A), A2pad = zero-pad(A @ A)
// grid (32,32), block (16,16)
// ---------------------------------------------------------------------------
__global__ __launch_bounds__(256) void kernelA(const float* __restrict__ A) {
    __shared__ float As[16][16];
    __shared__ float Bs[16][16];
    int tx = threadIdx.x, ty = threadIdx.y;
    int w = blockIdx.x * 16 + tx;
    int v = blockIdx.y * 16 + ty;
    float aval = (v < V_ && w < V_) ? A[v * V_ + w] : 0.f;
    float acc = 0.f;
    for (int u0 = 0; u0 < V_; u0 += 16) {
        int u1 = u0 + tx, u2 = u0 + ty;
        As[ty][tx] = (v < V_ && u1 < V_) ? A[v * V_ + u1] : 0.f;
        Bs[ty][tx] = (u2 < V_ && w < V_) ? A[u2 * V_ + w] : 0.f;
        __syncthreads();
#pragma unroll
        for (int u = 0; u < 16; u++) acc += As[ty][u] * Bs[u][tx];
        __syncthreads();
    }
    g_Apad [v * VP + w] = aval;
    g_A2pad[v * VP + w] = (v < V_ && w < V_) ? acc : 0.f;
}

// ---------------------------------------------------------------------------
// Kernel E: transpose w_out (64x96) -> g_Wt[k][o]
// grid 24, block 256
// ---------------------------------------------------------------------------
__global__ __launch_bounds__(256) void kernelE(const float* __restrict__ wout) {
    int idx = blockIdx.x * 256 + threadIdx.x;   // idx over 6144
    if (idx < 96 * 64) {
        int o = idx / 96, k = idx % 96;
        g_Wt[k * 64 + o] = wout[idx];
    }
}

// ---------------------------------------------------------------------------
// Kernel B: fused temporal conv gate
//   xt[n,c,v,l] = relu( conv1 + sigmoid(conv2) + conv3 )
// stored transposed: g_xt[n][c][l][v]
// grid (V_, N_), block 256
// ---------------------------------------------------------------------------
__global__ __launch_bounds__(256) void kernelB(
    const float* __restrict__ x,
    const float* __restrict__ w1, const float* __restrict__ b1,
    const float* __restrict__ w2, const float* __restrict__ b2,
    const float* __restrict__ w3, const float* __restrict__ b3)
{
    __shared__ __align__(16) float xs[CIN][T_];        // 12 KB
    __shared__ float ws[3][CIN * 3][CIN];              // ws[j][ci*3+k][c], 36 KB
    int v = blockIdx.x, n = blockIdx.y;
    int tid = threadIdx.x;

    // load x row strip: x[n, ci, v, 0..95]
    for (int idx = tid; idx < CIN * T_; idx += 256) {
        int ci = idx / T_, t = idx % T_;
        xs[ci][t] = x[((n * CIN + ci) * V_ + v) * T_ + t];
    }
    // load weights transposed: w[(c*32+ci)*3+k] -> ws[j][ci*3+k][c]
    for (int idx = tid; idx < CIN * CIN * 3; idx += 256) {
        int c = idx / (CIN * 3);
        int r = idx % (CIN * 3);
        ws[0][r][c] = w1[idx];
        ws[1][r][c] = w2[idx];
        ws[2][r][c] = w3[idx];
    }
    __syncthreads();

    int c = tid & 31;
    int g = tid >> 5;         // 0..7
    int l0 = g * 12;
    int lcnt = (L_ - l0 < 12) ? (L_ - l0) : 12;

    float acc0[12], acc1[12], acc2[12];
    float B0 = b1[c], B1 = b2[c], B2 = b3[c];
#pragma unroll
    for (int li = 0; li < 12; li++) { acc0[li] = B0; acc1[li] = B1; acc2[li] = B2; }

    for (int ci = 0; ci < CIN; ci++) {
        float xr[14];
#pragma unroll
        for (int t = 0; t < 14; t++) {
            int tt = l0 + t;
            xr[t] = xs[ci][tt < T_ ? tt : (T_ - 1)];   // clamp; clamped lanes feed discarded outputs only
        }
#pragma unroll
        for (int k = 0; k < 3; k++) {
            float w0r = ws[0][ci * 3 + k][c];
            float w1r = ws[1][ci * 3 + k][c];
            float w2r = ws[2][ci * 3 + k][c];
#pragma unroll
            for (int li = 0; li < 12; li++) {
                float xv = xr[li + k];
                acc0[li] = fmaf(w0r, xv, acc0[li]);
                acc1[li] = fmaf(w1r, xv, acc1[li]);
                acc2[li] = fmaf(w2r, xv, acc2[li]);
            }
        }
    }
    for (int li = 0; li < lcnt; li++) {
        float t = acc0[li] + 1.f / (1.f + __expf(-acc1[li]));
        float r = t + acc2[li];
        r = fmaxf(r, 0.f);
        g_xt[((n * CIN + c) * LP + (l0 + li)) * VP + v] = r;
    }
}

// ---------------------------------------------------------------------------
// Kernel C: diffusion GEMM.  Per n:  X12[mat] = XT(3008 x 512) @ Bpad(512 x 512)
// rows m = (c,l) c<32,l<94; B = Apad (mat 0) or A2pad (mat 1).
// Block tile 64x64, BK=16, 4x4 micro-tiles, 256 threads.
// grid (47, 16, 32): x = m-tile, y = mat*8 + w-tile, z = n
// ---------------------------------------------------------------------------
__global__ __launch_bounds__(256) void kernelC() {
    __shared__ __align__(16) float Ast[16][64];
    __shared__ __align__(16) float Bs [16][64];
    __shared__ int rowbase[64];
    __shared__ int obase  [64];

    int tid = threadIdx.x;
    int m0  = blockIdx.x * 64;
    int mat = blockIdx.y >> 3;
    int w0  = (blockIdx.y & 7) * 64;
    int n   = blockIdx.z;
    const float* __restrict__ B = mat ? g_A2pad : g_Apad;

    if (tid < 64) {
        int m = m0 + tid;
        int c = m / L_, l = m % L_;
        rowbase[tid] = ((n * CIN + c) * LP + l) * VP;
        obase  [tid] = (((mat * N_ + n) * CIN + c) * L_ + l) * VP;
    }
    __syncthreads();

    float acc[4][4] = {};
    int ty = tid >> 4, tx = tid & 15;
    int arow = tid >> 2, akq = tid & 3;
    int bkr  = tid >> 4, bwq = tid & 15;

    int abase = rowbase[arow];
    for (int k0 = 0; k0 < VP; k0 += 16) {
        float4 av = *(const float4*)&g_xt[abase + k0 + akq * 4];
        float4 bv = *(const float4*)&B[(k0 + bkr) * VP + w0 + bwq * 4];
        __syncthreads();   // previous iteration's reads done
        Ast[akq * 4 + 0][arow] = av.x;
        Ast[akq * 4 + 1][arow] = av.y;
        Ast[akq * 4 + 2][arow] = av.z;
        Ast[akq * 4 + 3][arow] = av.w;
        *(float4*)&Bs[bkr][bwq * 4] = bv;
        __syncthreads();
#pragma unroll
        for (int kk = 0; kk < 16; kk++) {
            float4 a4 = *(const float4*)&Ast[kk][ty * 4];
            float4 b4 = *(const float4*)&Bs [kk][tx * 4];
            float ar[4] = {a4.x, a4.y, a4.z, a4.w};
            float br[4] = {b4.x, b4.y, b4.z, b4.w};
#pragma unroll
            for (int i = 0; i < 4; i++)
#pragma unroll
                for (int j = 0; j < 4; j++)
                    acc[i][j] = fmaf(ar[i], br[j], acc[i][j]);
        }
    }
#pragma unroll
    for (int i = 0; i < 4; i++) {
        float4 o = make_float4(acc[i][0], acc[i][1], acc[i][2], acc[i][3]);
        *(float4*)&g_x12[obase[ty * 4 + i] + w0 + tx * 4] = o;
    }
}

// ---------------------------------------------------------------------------
// Kernel D: 1x1 projection (K=96) + bias + PReLU, write NCHW output.
// Block tile: 64 o  x  (32 w x 4 l).  grid (16, 24, 32), 256 threads.
// ---------------------------------------------------------------------------
__global__ __launch_bounds__(256) void kernelD(
    const float* __restrict__ bout,
    const float* __restrict__ pa,
    float* __restrict__ out)
{
    __shared__ __align__(16) float Xs[96][128];   // 48 KB; col j = wi*4 + li

    int n  = blockIdx.z;
    int w0 = blockIdx.x * 32;
    int l0 = blockIdx.y * 4;
    int tid = threadIdx.x;

    for (int idx = tid; idx < 96 * 128; idx += 256) {
        int r   = idx >> 7;          // hop*32 + c
        int rem = idx & 127;
        int li  = rem >> 5;
        int wi  = rem & 31;
        int hop = r >> 5, c = r & 31;
        int l = l0 + li, w = w0 + wi;   // w < 512 always; pad cols are zero
        float val = 0.f;
        if (l < L_) {
            if (hop == 0)
                val = g_xt[((n * CIN + c) * LP + l) * VP + w];
            else
                val = g_x12[((((hop - 1) * N_ + n) * CIN + c) * L_ + l) * VP + w];
        }
        Xs[r][wi * 4 + li] = val;
    }
    __syncthreads();

    int to = tid & 15;    // o block: o = to*4 + i
    int tj = tid >> 4;    // col block: j = tj*8 + jj
    float acc[4][8] = {};
#pragma unroll 4
    for (int k = 0; k < 96; k++) {
        float4 wv = *(const float4*)&g_Wt[k * 64 + to * 4];
#pragma unroll
        for (int jj = 0; jj < 8; jj++) {
            float xv = Xs[k][tj * 8 + jj];
            acc[0][jj] = fmaf(wv.x, xv, acc[0][jj]);
            acc[1][jj] = fmaf(wv.y, xv, acc[1][jj]);
            acc[2][jj] = fmaf(wv.z, xv, acc[2][jj]);
            acc[3][jj] = fmaf(wv.w, xv, acc[3][jj]);
        }
    }
    float a = pa[0];
#pragma unroll
    for (int i = 0; i < 4; i++) {
        int o = to * 4 + i;
        float b = bout[o];
#pragma unroll
        for (int jj = 0; jj < 8; jj++) {
            int j  = tj * 8 + jj;
            int wi = j >> 2, li = j & 3;
            int w = w0 + wi, l = l0 + li;
            if (w < V_ && l < L_) {
                float vv = acc[i][jj] + b;
                out[((n * COUT + o) * V_ + w) * L_ + l] = vv > 0.f ? vv : a * vv;
            }
        }
    }
}

// ---------------------------------------------------------------------------
extern "C" void kernel_launch(void* const* d_in, const int* in_sizes, int n_in,
                              void* d_out, int out_size) {
    const float* x    = (const float*)d_in[0];
    const float* A    = (const float*)d_in[1];
    const float* w1   = (const float*)d_in[2];
    const float* b1   = (const float*)d_in[3];
    const float* w2   = (const float*)d_in[4];
    const float* b2   = (const float*)d_in[5];
    const float* w3   = (const float*)d_in[6];
    const float* b3   = (const float*)d_in[7];
    const float* wout = (const float*)d_in[8];
    const float* bout = (const float*)d_in[9];
    const float* pa   = (const float*)d_in[10];
    float* out = (float*)d_out;

    kernelA<<<dim3(32, 32), dim3(16, 16)>>>(A);
    kernelE<<<24, 256>>>(wout);
    kernelB<<<dim3(V_, N_), 256>>>(x, w1, b1, w2, b2, w3, b3);
    kernelC<<<dim3(47, 16, 32), 256>>>();
    kernelD<<<dim3(16, 24, 32), 256>>>(bout, pa, out);
}

// round 3
// speedup vs baseline: 1.6179x; 1.6179x over previous
#include <cuda_runtime.h>
#include <cuda_bf16.h>

#define N_    32
#define CIN   32
#define V_    500
#define T_    96
#define L_    94      // T - K + 1
#define COUT  64
#define VP    512     // padded v/w dim
#define LP    96      // padded l dim in g_xt

// Scratch (zero-initialized at module load; padding regions never written)
__device__ float          g_xt  [N_ * CIN * LP * VP];     // [n][c][l][v] fp32
__device__ __nv_bfloat16  g_xtb [N_ * CIN * LP * VP];     // bf16 copy
__device__ float          g_x12 [2 * N_ * CIN * L_ * VP]; // [mat][n][c][l][w]
__device__ float          g_Apad [VP * VP];               // zero-padded A (fallback)
__device__ float          g_A2pad[VP * VP];               // zero-padded A@A (fallback)
__device__ __nv_bfloat16  g_ATb [VP * VP];                // A^T   (w-major, K=v)
__device__ __nv_bfloat16  g_A2Tb[VP * VP];                // (A@A)^T
__device__ float          g_Wt  [96 * 64];                // Wt[k][o] = w_out[o][k]

#define HAS_TCGEN05 (defined(__CUDA_ARCH_FEAT_SM103_ALL) || defined(__CUDA_ARCH_FEAT_SM100_ALL) || defined(__CUDA_ARCH_FEAT_SM101_ALL))

// ---------------------------------------------------------------------------
// PTX helpers (only compiled into arch-specific passes that support tcgen05)
// ---------------------------------------------------------------------------
#define SW128(o) ((o) ^ (((o) >> 3) & 0x70))

static __device__ __forceinline__ unsigned smem_u32(const void* p) {
    unsigned a;
    asm("{ .reg .u64 t; cvta.to.shared.u64 t, %1; cvt.u32.u64 %0, t; }"
        : "=r"(a) : "l"(p));
    return a;
}

#if HAS_TCGEN05
static __device__ __forceinline__ unsigned elect_one() {
    unsigned p;
    asm volatile("{\n\t.reg .pred p;\n\telect.sync _|p, 0xFFFFFFFF;\n\t"
                 "selp.b32 %0, 1, 0, p;\n\t}" : "=r"(p));
    return p;
}

static __device__ __forceinline__ void mbar_wait_parity(unsigned mbar, unsigned phase) {
    asm volatile(
        "{\n\t.reg .pred P1;\n\t"
        "WL_%=:\n\t"
        "mbarrier.try_wait.parity.acquire.cta.shared::cta.b64 P1, [%0], %1, 0x989680;\n\t"
        "@P1 bra.uni WD_%=;\n\t"
        "bra.uni WL_%=;\n\t"
        "WD_%=:\n\t}"
        :: "r"(mbar), "r"(phase) : "memory");
}

static __device__ __forceinline__ void mma_bf16_ss(unsigned d_tmem, unsigned long long a_desc,
                                                   unsigned long long b_desc, unsigned idesc,
                                                   unsigned en) {
    asm volatile(
        "{\n\t.reg .pred p;\n\t"
        "setp.ne.u32 p, %4, 0;\n\t"
        "tcgen05.mma.cta_group::1.kind::f16 [%0], %1, %2, %3, {%5, %5, %5, %5}, p;\n\t}"
        :: "r"(d_tmem), "l"(a_desc), "l"(b_desc), "r"(idesc), "r"(en), "r"(0u)
        : "memory");
}

static __device__ __forceinline__ void ldtm_x32(unsigned* r, unsigned addr) {
    asm volatile(
        "tcgen05.ld.sync.aligned.32x32b.x32.b32 "
        "{%0, %1, %2, %3, %4, %5, %6, %7, "
        " %8, %9, %10, %11, %12, %13, %14, %15, "
        " %16, %17, %18, %19, %20, %21, %22, %23, "
        " %24, %25, %26, %27, %28, %29, %30, %31}, [%32];"
        : "=r"(r[0]),  "=r"(r[1]),  "=r"(r[2]),  "=r"(r[3]),
          "=r"(r[4]),  "=r"(r[5]),  "=r"(r[6]),  "=r"(r[7]),
          "=r"(r[8]),  "=r"(r[9]),  "=r"(r[10]), "=r"(r[11]),
          "=r"(r[12]), "=r"(r[13]), "=r"(r[14]), "=r"(r[15]),
          "=r"(r[16]), "=r"(r[17]), "=r"(r[18]), "=r"(r[19]),
          "=r"(r[20]), "=r"(r[21]), "=r"(r[22]), "=r"(r[23]),
          "=r"(r[24]), "=r"(r[25]), "=r"(r[26]), "=r"(r[27]),
          "=r"(r[28]), "=r"(r[29]), "=r"(r[30]), "=r"(r[31])
        : "r"(addr));
}

// SW128 K-major descriptor: layout=2, version=1, SBO=64 (1024B per 8-row group), LBO=1
#define DESC_BASE ((2ULL << 61) | (1ULL << 46) | (64ULL << 32) | (1ULL << 16))
#endif  // HAS_TCGEN05

// ---------------------------------------------------------------------------
// Kernel A: A@A in fp32; emit fp32 zero-padded A/A2 AND bf16 transposed A^T/(A@A)^T
// grid (32,32), block (16,16) -> covers 512x512
// ---------------------------------------------------------------------------
__global__ __launch_bounds__(256) void kernelA(const float* __restrict__ A) {
    __shared__ float As[16][16];
    __shared__ float Bs[16][16];
    int tx = threadIdx.x, ty = threadIdx.y;
    int w = blockIdx.x * 16 + tx;
    int v = blockIdx.y * 16 + ty;
    float aval = (v < V_ && w < V_) ? A[v * V_ + w] : 0.f;
    float acc = 0.f;
    for (int u0 = 0; u0 < V_; u0 += 16) {
        int u1 = u0 + tx, u2 = u0 + ty;
        As[ty][tx] = (v < V_ && u1 < V_) ? A[v * V_ + u1] : 0.f;
        Bs[ty][tx] = (u2 < V_ && w < V_) ? A[u2 * V_ + w] : 0.f;
        __syncthreads();
#pragma unroll
        for (int u = 0; u < 16; u++) acc += As[ty][u] * Bs[u][tx];
        __syncthreads();
    }
    float a2val = (v < V_ && w < V_) ? acc : 0.f;
    g_Apad [v * VP + w] = aval;
    g_A2pad[v * VP + w] = a2val;
    // transposed bf16: row = w, col = v
    g_ATb [w * VP + v] = __float2bfloat16(aval);
    g_A2Tb[w * VP + v] = __float2bfloat16(a2val);
}

// ---------------------------------------------------------------------------
// Kernel E: transpose w_out (64x96) -> g_Wt[k][o]
// ---------------------------------------------------------------------------
__global__ __launch_bounds__(256) void kernelE(const float* __restrict__ wout) {
    int idx = blockIdx.x * 256 + threadIdx.x;
    if (idx < 96 * 64) {
        int o = idx / 96, k = idx % 96;
        g_Wt[k * 64 + o] = wout[idx];
    }
}

// ---------------------------------------------------------------------------
// Kernel B: fused temporal conv gate -> g_xt (fp32) + g_xtb (bf16), [n][c][l][v]
// grid (V_, N_), block 256
// ---------------------------------------------------------------------------
__global__ __launch_bounds__(256) void kernelB(
    const float* __restrict__ x,
    const float* __restrict__ w1, const float* __restrict__ b1,
    const float* __restrict__ w2, const float* __restrict__ b2,
    const float* __restrict__ w3, const float* __restrict__ b3)
{
    __shared__ __align__(16) float xs[CIN][T_];
    __shared__ float ws[3][CIN * 3][CIN];
    int v = blockIdx.x, n = blockIdx.y;
    int tid = threadIdx.x;

    for (int idx = tid; idx < CIN * T_; idx += 256) {
        int ci = idx / T_, t = idx % T_;
        xs[ci][t] = x[((n * CIN + ci) * V_ + v) * T_ + t];
    }
    for (int idx = tid; idx < CIN * CIN * 3; idx += 256) {
        int c = idx / (CIN * 3);
        int r = idx % (CIN * 3);
        ws[0][r][c] = w1[idx];
        ws[1][r][c] = w2[idx];
        ws[2][r][c] = w3[idx];
    }
    __syncthreads();

    int c = tid & 31;
    int g = tid >> 5;
    int l0 = g * 12;
    int lcnt = (L_ - l0 < 12) ? (L_ - l0) : 12;

    float acc0[12], acc1[12], acc2[12];
    float B0 = b1[c], B1 = b2[c], B2 = b3[c];
#pragma unroll
    for (int li = 0; li < 12; li++) { acc0[li] = B0; acc1[li] = B1; acc2[li] = B2; }

    for (int ci = 0; ci < CIN; ci++) {
        float xr[14];
#pragma unroll
        for (int t = 0; t < 14; t++) {
            int tt = l0 + t;
            xr[t] = xs[ci][tt < T_ ? tt : (T_ - 1)];
        }
#pragma unroll
        for (int k = 0; k < 3; k++) {
            float w0r = ws[0][ci * 3 + k][c];
            float w1r = ws[1][ci * 3 + k][c];
            float w2r = ws[2][ci * 3 + k][c];
#pragma unroll
            for (int li = 0; li < 12; li++) {
                float xv = xr[li + k];
                acc0[li] = fmaf(w0r, xv, acc0[li]);
                acc1[li] = fmaf(w1r, xv, acc1[li]);
                acc2[li] = fmaf(w2r, xv, acc2[li]);
            }
        }
    }
    for (int li = 0; li < lcnt; li++) {
        float t = acc0[li] + 1.f / (1.f + __expf(-acc1[li]));
        float r = t + acc2[li];
        r = fmaxf(r, 0.f);
        int idx = ((n * CIN + c) * LP + (l0 + li)) * VP + v;
        g_xt [idx] = r;
        g_xtb[idx] = __float2bfloat16(r);
    }
}

// ---------------------------------------------------------------------------
// Kernel C: diffusion GEMM, 128x128 output tile per CTA, K = 512 (padded).
//   X12[mat][n][m=(c,l)][w] = sum_v xt[n][m][v] * A^(mat+1)[v][w]
// grid (24, 8, 32): x = m-tile, y = mat*4 + w-tile, z = n.  256 threads.
// tcgen05 bf16 path on sm_103a; SIMT fp32 8x8 fallback otherwise.
// ---------------------------------------------------------------------------
#define C_SMEM_BYTES (1024 + 2 * 16384 + 64)

#if HAS_TCGEN05
#define KC_BOUNDS __launch_bounds__(256, 4)
#else
#define KC_BOUNDS __launch_bounds__(256, 1)
#endif

__global__ KC_BOUNDS void kernelC() {
    extern __shared__ char smem[];
    __shared__ int rowbase[128];
    __shared__ int obase[128];

    int tid = threadIdx.x, wid = tid >> 5, lid = tid & 31;
    int m0  = blockIdx.x * 128;
    int mat = blockIdx.y >> 2;
    int w0  = (blockIdx.y & 3) * 128;
    int n   = blockIdx.z;

    if (tid < 128) {
        int m = m0 + tid;
        bool valid = m < CIN * L_;
        int mm = valid ? m : 0;
        int c = mm / L_, l = mm % L_;
        rowbase[tid] = ((n * CIN + c) * LP + l) * VP;
        obase[tid]   = valid ? ((((mat * N_ + n) * CIN + c) * L_ + l) * VP) : -1;
    }

#if HAS_TCGEN05
    // ---------------- tcgen05 bf16 SS path ----------------
    unsigned s0 = smem_u32(smem);
    unsigned sA = (s0 + 1023) & ~1023u;     // 1024-aligned for SW128 desc
    unsigned sB = sA + 16384;
    unsigned sCtl = sA + 32768;             // [0:4) tmem ptr, [8:16) mbar
    char* pA = smem + (sA - s0);
    char* pB = smem + (sB - s0);
    const __nv_bfloat16* __restrict__ Bm = mat ? g_A2Tb : g_ATb;

    if (wid == 0) {
        asm volatile("tcgen05.alloc.cta_group::1.sync.aligned.shared::cta.b32 [%0], %1;"
                     :: "r"(sCtl), "r"(128) : "memory");
        asm volatile("tcgen05.relinquish_alloc_permit.cta_group::1.sync.aligned;");
    }
    if (tid == 0) {
        asm volatile("mbarrier.init.shared.b64 [%0], %1;" :: "r"(sCtl + 8), "r"(1) : "memory");
    }
    __syncthreads();
    unsigned tmem;
    asm volatile("ld.shared.b32 %0, [%1];" : "=r"(tmem) : "r"(sCtl));

    const unsigned idesc = 0x490u | (16u << 17) | (8u << 24);   // F32 acc, bf16xbf16, N=128, M=128
    unsigned long long adesc0 = DESC_BASE | ((unsigned long long)(sA >> 4) & 0x3FFF);
    unsigned long long bdesc0 = DESC_BASE | ((unsigned long long)(sB >> 4) & 0x3FFF);

    for (int kc = 0; kc < 8; kc++) {
        int k0 = kc * 64;
#pragma unroll
        for (int it = 0; it < 4; it++) {
            int idx = tid + it * 256;            // 0..1023
            int row = idx >> 3, c16 = idx & 7;
            unsigned off = row * 128 + c16 * 16;
            unsigned sw = SW128(off);
            float4 va = *(const float4*)(&g_xtb[rowbase[row] + k0 + c16 * 8]);
            *(float4*)(pA + sw) = va;
            float4 vb = *(const float4*)(&Bm[(w0 + row) * VP + k0 + c16 * 8]);
            *(float4*)(pB + sw) = vb;
        }
        asm volatile("fence.proxy.async.shared::cta;" ::: "memory");
        __syncthreads();
        if (wid == 0 && elect_one()) {
#pragma unroll
            for (int j = 0; j < 4; j++) {        // 4 x K=16 steps per 64-chunk
                mma_bf16_ss(tmem, adesc0 + j * 2, bdesc0 + j * 2, idesc,
                            (kc > 0 || j > 0) ? 1u : 0u);
            }
            asm volatile(
                "tcgen05.commit.cta_group::1.mbarrier::arrive::one.shared::cluster.b64 [%0];"
                :: "r"(sCtl + 8) : "memory");
        }
        mbar_wait_parity(sCtl + 8, (unsigned)(kc & 1));
    }

    asm volatile("tcgen05.fence::after_thread_sync;" ::: "memory");

    if (wid < 4) {
        int row = wid * 32 + lid;
        int ob = obase[row];
#pragma unroll
        for (int g = 0; g < 4; g++) {
            unsigned r[32];
            ldtm_x32(r, tmem + g * 32);
            asm volatile("tcgen05.wait::ld.sync.aligned;" ::: "memory");
            if (ob >= 0) {
#pragma unroll
                for (int q = 0; q < 8; q++) {
                    float4 o = make_float4(__uint_as_float(r[q * 4 + 0]),
                                           __uint_as_float(r[q * 4 + 1]),
                                           __uint_as_float(r[q * 4 + 2]),
                                           __uint_as_float(r[q * 4 + 3]));
                    *(float4*)&g_x12[ob + w0 + g * 32 + q * 4] = o;
                }
            }
        }
    }
    __syncthreads();
    if (tid == 0)
        asm volatile("mbarrier.inval.shared.b64 [%0];" :: "r"(sCtl + 8) : "memory");
    if (wid == 0)
        asm volatile("tcgen05.dealloc.cta_group::1.sync.aligned.b32 %0, %1;"
                     :: "r"(tmem), "r"(128));

#else
    // ---------------- SIMT fp32 fallback: 128x128 tile, 8x8 micro ----------------
    (void)wid; (void)lid;
    float* As = (float*)smem;                 // [16][132]
    float* Bs = As + 16 * 132;                // [16][132]
    const float* __restrict__ Bmf = mat ? g_A2pad : g_Apad;
    __syncthreads();

    int ty = tid >> 4, tx = tid & 15;         // 16x16 threads, each 8x8
    float acc[8][8] = {};

    for (int k0 = 0; k0 < VP; k0 += 16) {
        __syncthreads();
#pragma unroll
        for (int it = 0; it < 2; it++) {
            int i = tid + it * 256;           // 0..511
            // A: 128 rows x 16 k  (load float4 along k, transpose-store)
            int arow = i >> 2, aq = i & 3;
            float4 va = *(const float4*)&g_xt[rowbase[arow] + k0 + aq * 4];
            As[(aq * 4 + 0) * 132 + arow] = va.x;
            As[(aq * 4 + 1) * 132 + arow] = va.y;
            As[(aq * 4 + 2) * 132 + arow] = va.z;
            As[(aq * 4 + 3) * 132 + arow] = va.w;
            // B: 16 k-rows x 128 w
            int bk = i >> 5, bw = (i & 31) * 4;
            float4 vb = *(const float4*)&Bmf[(k0 + bk) * VP + w0 + bw];
            *(float4*)&Bs[bk * 132 + bw] = vb;
        }
        __syncthreads();
#pragma unroll
        for (int kk = 0; kk < 16; kk++) {
            float4 a0 = *(const float4*)&As[kk * 132 + ty * 8];
            float4 a1 = *(const float4*)&As[kk * 132 + ty * 8 + 4];
            float4 b0 = *(const float4*)&Bs[kk * 132 + tx * 8];
            float4 b1 = *(const float4*)&Bs[kk * 132 + tx * 8 + 4];
            float ar[8] = {a0.x, a0.y, a0.z, a0.w, a1.x, a1.y, a1.z, a1.w};
            float br[8] = {b0.x, b0.y, b0.z, b0.w, b1.x, b1.y, b1.z, b1.w};
#pragma unroll
            for (int i = 0; i < 8; i++)
#pragma unroll
                for (int j = 0; j < 8; j++)
                    acc[i][j] = fmaf(ar[i], br[j], acc[i][j]);
        }
    }
#pragma unroll
    for (int i = 0; i < 8; i++) {
        int ob = obase[ty * 8 + i];
        if (ob >= 0) {
            *(float4*)&g_x12[ob + w0 + tx * 8]     = make_float4(acc[i][0], acc[i][1], acc[i][2], acc[i][3]);
            *(float4*)&g_x12[ob + w0 + tx * 8 + 4] = make_float4(acc[i][4], acc[i][5], acc[i][6], acc[i][7]);
        }
    }
#endif
}

// ---------------------------------------------------------------------------
// Kernel D: 1x1 projection (K=96) + bias + PReLU, write NCHW output.
// grid (16, 24, 32), 256 threads.
// ---------------------------------------------------------------------------
__global__ __launch_bounds__(256) void kernelD(
    const float* __restrict__ bout,
    const float* __restrict__ pa,
    float* __restrict__ out)
{
    __shared__ __align__(16) float Xs[96][128];   // col j = wi*4 + li

    int n  = blockIdx.z;
    int w0 = blockIdx.x * 32;
    int l0 = blockIdx.y * 4;
    int tid = threadIdx.x;

    for (int idx = tid; idx < 96 * 128; idx += 256) {
        int r   = idx >> 7;
        int rem = idx & 127;
        int li  = rem >> 5;
        int wi  = rem & 31;
        int hop = r >> 5, c = r & 31;
        int l = l0 + li, w = w0 + wi;
        float val = 0.f;
        if (l < L_) {
            if (hop == 0)
                val = g_xt[((n * CIN + c) * LP + l) * VP + w];
            else
                val = g_x12[((((hop - 1) * N_ + n) * CIN + c) * L_ + l) * VP + w];
        }
        Xs[r][wi * 4 + li] = val;
    }
    __syncthreads();

    int to = tid & 15;
    int tj = tid >> 4;
    float acc[4][8] = {};
#pragma unroll 4
    for (int k = 0; k < 96; k++) {
        float4 wv = *(const float4*)&g_Wt[k * 64 + to * 4];
#pragma unroll
        for (int jj = 0; jj < 8; jj++) {
            float xv = Xs[k][tj * 8 + jj];
            acc[0][jj] = fmaf(wv.x, xv, acc[0][jj]);
            acc[1][jj] = fmaf(wv.y, xv, acc[1][jj]);
            acc[2][jj] = fmaf(wv.z, xv, acc[2][jj]);
            acc[3][jj] = fmaf(wv.w, xv, acc[3][jj]);
        }
    }
    float a = pa[0];
#pragma unroll
    for (int i = 0; i < 4; i++) {
        int o = to * 4 + i;
        float b = bout[o];
#pragma unroll
        for (int jj = 0; jj < 8; jj++) {
            int j  = tj * 8 + jj;
            int wi = j >> 2, li = j & 3;
            int w = w0 + wi, l = l0 + li;
            if (w < V_ && l < L_) {
                float vv = acc[i][jj] + b;
                out[((n * COUT + o) * V_ + w) * L_ + l] = vv > 0.f ? vv : a * vv;
            }
        }
    }
}

// ---------------------------------------------------------------------------
extern "C" void kernel_launch(void* const* d_in, const int* in_sizes, int n_in,
                              void* d_out, int out_size) {
    const float* x    = (const float*)d_in[0];
    const float* A    = (const float*)d_in[1];
    const float* w1   = (const float*)d_in[2];
    const float* b1   = (const float*)d_in[3];
    const float* w2   = (const float*)d_in[4];
    const float* b2   = (const float*)d_in[5];
    const float* w3   = (const float*)d_in[6];
    const float* b3   = (const float*)d_in[7];
    const float* wout = (const float*)d_in[8];
    const float* bout = (const float*)d_in[9];
    const float* pa   = (const float*)d_in[10];
    float* out = (float*)d_out;

    static int smem_set = 0;
    if (!smem_set) {
        cudaFuncSetAttribute(kernelC, cudaFuncAttributeMaxDynamicSharedMemorySize, C_SMEM_BYTES);
        smem_set = 1;
    }

    kernelA<<<dim3(32, 32), dim3(16, 16)>>>(A);
    kernelE<<<24, 256>>>(wout);
    kernelB<<<dim3(V_, N_), 256>>>(x, w1, b1, w2, b2, w3, b3);
    kernelC<<<dim3(24, 8, 32), 256, C_SMEM_BYTES>>>();
    kernelD<<<dim3(16, 24, 32), 256>>>(bout, pa, out);
}

// round 4
// speedup vs baseline: 2.2516x; 1.3917x over previous
#include <cuda_runtime.h>
#include <cuda_bf16.h>

#define N_    32
#define CIN   32
#define V_    500
#define T_    96
#define L_    94      // T - K + 1
#define COUT  64
#define VP    512     // padded v/w dim
#define LP    96      // padded l dim in g_xt

// Scratch (zero-initialized at module load; padding regions never written)
__device__ float          g_xt  [N_ * CIN * LP * VP];     // [n][c][l][v] fp32
__device__ __nv_bfloat16  g_xtb [N_ * CIN * LP * VP];     // bf16 copy
__device__ float          g_x12 [2 * N_ * CIN * L_ * VP]; // [mat][n][c][l][w]
__device__ float          g_Apad [VP * VP];               // zero-padded A (fallback)
__device__ float          g_A2pad[VP * VP];               // zero-padded A@A (fallback)
__device__ __nv_bfloat16  g_ATb [VP * VP];                // A^T   (w-major, K=v)
__device__ __nv_bfloat16  g_A2Tb[VP * VP];                // (A@A)^T
__device__ float          g_Wt  [96 * 64];                // Wt[k][o] = w_out[o][k]
__device__ float          g_xp  [N_ * VP * T_ * CIN];     // x transposed [n][v][t][ci], tf32-rounded
__device__ float          g_Wcat[128 * 96];               // stacked conv weights, tf32-rounded

#define HAS_TCGEN05 (defined(__CUDA_ARCH_FEAT_SM103_ALL) || defined(__CUDA_ARCH_FEAT_SM100_ALL) || defined(__CUDA_ARCH_FEAT_SM101_ALL))

// ---------------------------------------------------------------------------
#define SW128(o) ((o) ^ (((o) >> 3) & 0x70))

static __device__ __forceinline__ unsigned smem_u32(const void* p) {
    unsigned a;
    asm("{ .reg .u64 t; cvta.to.shared.u64 t, %1; cvt.u32.u64 %0, t; }"
        : "=r"(a) : "l"(p));
    return a;
}

static __device__ __forceinline__ float tf32r(float x) {
    float r;
    asm("cvt.rna.tf32.f32 %0, %1;" : "=f"(r) : "f"(x));
    return r;
}

#if HAS_TCGEN05
static __device__ __forceinline__ unsigned elect_one() {
    unsigned p;
    asm volatile("{\n\t.reg .pred p;\n\telect.sync _|p, 0xFFFFFFFF;\n\t"
                 "selp.b32 %0, 1, 0, p;\n\t}" : "=r"(p));
    return p;
}

static __device__ __forceinline__ void mbar_wait_parity(unsigned mbar, unsigned phase) {
    asm volatile(
        "{\n\t.reg .pred P1;\n\t"
        "WL_%=:\n\t"
        "mbarrier.try_wait.parity.acquire.cta.shared::cta.b64 P1, [%0], %1, 0x989680;\n\t"
        "@P1 bra.uni WD_%=;\n\t"
        "bra.uni WL_%=;\n\t"
        "WD_%=:\n\t}"
        :: "r"(mbar), "r"(phase) : "memory");
}

static __device__ __forceinline__ void mma_bf16_ss(unsigned d_tmem, unsigned long long a_desc,
                                                   unsigned long long b_desc, unsigned idesc,
                                                   unsigned en) {
    asm volatile(
        "{\n\t.reg .pred p;\n\t"
        "setp.ne.u32 p, %4, 0;\n\t"
        "tcgen05.mma.cta_group::1.kind::f16 [%0], %1, %2, %3, {%5, %5, %5, %5}, p;\n\t}"
        :: "r"(d_tmem), "l"(a_desc), "l"(b_desc), "r"(idesc), "r"(en), "r"(0u)
        : "memory");
}

static __device__ __forceinline__ void mma_tf32_ss(unsigned d_tmem, unsigned long long a_desc,
                                                   unsigned long long b_desc, unsigned idesc,
                                                   unsigned en) {
    asm volatile(
        "{\n\t.reg .pred p;\n\t"
        "setp.ne.u32 p, %4, 0;\n\t"
        "tcgen05.mma.cta_group::1.kind::tf32 [%0], %1, %2, %3, {%5, %5, %5, %5}, p;\n\t}"
        :: "r"(d_tmem), "l"(a_desc), "l"(b_desc), "r"(idesc), "r"(en), "r"(0u)
        : "memory");
}

static __device__ __forceinline__ void ldtm_x32(unsigned* r, unsigned addr) {
    asm volatile(
        "tcgen05.ld.sync.aligned.32x32b.x32.b32 "
        "{%0, %1, %2, %3, %4, %5, %6, %7, "
        " %8, %9, %10, %11, %12, %13, %14, %15, "
        " %16, %17, %18, %19, %20, %21, %22, %23, "
        " %24, %25, %26, %27, %28, %29, %30, %31}, [%32];"
        : "=r"(r[0]),  "=r"(r[1]),  "=r"(r[2]),  "=r"(r[3]),
          "=r"(r[4]),  "=r"(r[5]),  "=r"(r[6]),  "=r"(r[7]),
          "=r"(r[8]),  "=r"(r[9]),  "=r"(r[10]), "=r"(r[11]),
          "=r"(r[12]), "=r"(r[13]), "=r"(r[14]), "=r"(r[15]),
          "=r"(r[16]), "=r"(r[17]), "=r"(r[18]), "=r"(r[19]),
          "=r"(r[20]), "=r"(r[21]), "=r"(r[22]), "=r"(r[23]),
          "=r"(r[24]), "=r"(r[25]), "=r"(r[26]), "=r"(r[27]),
          "=r"(r[28]), "=r"(r[29]), "=r"(r[30]), "=r"(r[31])
        : "r"(addr));
}

// SW128 K-major descriptor: layout=2, version=1, SBO=64 (1024B per 8-row group), LBO=1
#define DESC_BASE ((2ULL << 61) | (1ULL << 46) | (64ULL << 32) | (1ULL << 16))
#endif  // HAS_TCGEN05

// ---------------------------------------------------------------------------
// Kernel A: A@A in fp32; emit fp32 zero-padded A/A2 AND bf16 transposed A^T/(A@A)^T
// ---------------------------------------------------------------------------
__global__ __launch_bounds__(256) void kernelA(const float* __restrict__ A) {
    __shared__ float As[16][16];
    __shared__ float Bs[16][16];
    int tx = threadIdx.x, ty = threadIdx.y;
    int w = blockIdx.x * 16 + tx;
    int v = blockIdx.y * 16 + ty;
    float aval = (v < V_ && w < V_) ? A[v * V_ + w] : 0.f;
    float acc = 0.f;
    for (int u0 = 0; u0 < V_; u0 += 16) {
        int u1 = u0 + tx, u2 = u0 + ty;
        As[ty][tx] = (v < V_ && u1 < V_) ? A[v * V_ + u1] : 0.f;
        Bs[ty][tx] = (u2 < V_ && w < V_) ? A[u2 * V_ + w] : 0.f;
        __syncthreads();
#pragma unroll
        for (int u = 0; u < 16; u++) acc += As[ty][u] * Bs[u][tx];
        __syncthreads();
    }
    float a2val = (v < V_ && w < V_) ? acc : 0.f;
    g_Apad [v * VP + w] = aval;
    g_A2pad[v * VP + w] = a2val;
    g_ATb [w * VP + v] = __float2bfloat16(aval);
    g_A2Tb[w * VP + v] = __float2bfloat16(a2val);
}

// ---------------------------------------------------------------------------
// Kernel E: transpose w_out -> g_Wt[k][o]
// ---------------------------------------------------------------------------
__global__ __launch_bounds__(256) void kernelE(const float* __restrict__ wout) {
    int idx = blockIdx.x * 256 + threadIdx.x;
    if (idx < 96 * 64) {
        int o = idx / 96, k = idx % 96;
        g_Wt[k * 64 + o] = wout[idx];
    }
}

// ---------------------------------------------------------------------------
// Kernel W: build g_Wcat[row][k'] : rows 0-31 conv1, 32-63 conv2, 64-95 conv3,
// 96-127 zero; k' = kk*32 + ci; tf32-rounded.  grid 48, block 256
// ---------------------------------------------------------------------------
__global__ __launch_bounds__(256) void kernelW(
    const float* __restrict__ w1, const float* __restrict__ w2,
    const float* __restrict__ w3)
{
    int idx = blockIdx.x * 256 + threadIdx.x;
    if (idx < 128 * 96) {
        int row = idx / 96, kp = idx % 96;
        int kk = kp >> 5, ci = kp & 31;
        float val = 0.f;
        if (row < 32)       val = w1[row * 96 + ci * 3 + kk];
        else if (row < 64)  val = w2[(row - 32) * 96 + ci * 3 + kk];
        else if (row < 96)  val = w3[(row - 64) * 96 + ci * 3 + kk];
        g_Wcat[idx] = tf32r(val);
    }
}

// ---------------------------------------------------------------------------
// Kernel X: transpose x[n][ci][v][t] -> g_xp[n][v][t][ci] (tf32-rounded).
// grid (125, 32): block handles 4 v's.  smem tile [4][96][33] padded.
// ---------------------------------------------------------------------------
#define X_SMEM (4 * 96 * 33 * 4)
__global__ __launch_bounds__(256) void kernelX(const float* __restrict__ x) {
    extern __shared__ float xs[];          // [vi][t][33] : [4][96][33]
    int v0 = blockIdx.x * 4, n = blockIdx.y;
    int tid = threadIdx.x;
    // load: t contiguous per (ci, vi)
    for (int i = tid; i < CIN * 4 * T_; i += 256) {
        int t  = i % T_;
        int r  = i / T_;
        int vi = r & 3;
        int ci = r >> 2;
        xs[(vi * T_ + t) * 33 + ci] = x[((n * CIN + ci) * V_ + v0 + vi) * T_ + t];
    }
    __syncthreads();
    // store: ci contiguous per (v, t)
    for (int i = tid; i < 4 * T_ * CIN; i += 256) {
        int ci = i & 31;
        int r  = i >> 5;
        int t  = r % T_;
        int vi = r / T_;
        g_xp[((n * VP + v0 + vi) * T_ + t) * CIN + ci] = tf32r(xs[(vi * T_ + t) * 33 + ci]);
    }
}

// ---------------------------------------------------------------------------
// Kernel B (tcgen05 tf32): fused temporal conv gate as MMA.
//   D[row][j=v] = sum_{k'=96} Wcat[row][k'] * xp[n][v][l + k'/32][k'%32]
//   rows 0-31/32-63/64-95 = conv1/2/3; epilogue: relu(c1+b1 + sigmoid(c2+b2) + c3+b3)
// grid (4, 94, 32): x = vchunk(128), y = l, z = n.  256 threads.
// SMEM: A-tile 48KB + B-tile 48KB (3 atom-cols of SW128, K=96 tf32), reuse for combine.
// ---------------------------------------------------------------------------
#define BM_SMEM (1024 + 2 * 49152 + 64)

__global__ __launch_bounds__(256) void kernelB_mma(
    const float* __restrict__ b1, const float* __restrict__ b2,
    const float* __restrict__ b3)
{
    int tid = threadIdx.x, wid = tid >> 5, lid = tid & 31;
    int v0 = blockIdx.x * 128;
    int l  = blockIdx.y;
    int n  = blockIdx.z;
    int nv = (V_ - v0 < 128) ? (V_ - v0) : 128;

#if HAS_TCGEN05
    extern __shared__ char smem[];
    unsigned s0 = smem_u32(smem);
    unsigned sA = (s0 + 1023) & ~1023u;
    unsigned sB = sA + 49152;
    unsigned sCtl = sA + 98304;            // [0:4) tmem ptr, [8:16) mbar
    char* pA = smem + (sA - s0);
    char* pB = smem + (sB - s0);
    float* sC = (float*)pA;                // combine stage [96 rows][132] after MMA

    if (wid == 0) {
        asm volatile("tcgen05.alloc.cta_group::1.sync.aligned.shared::cta.b32 [%0], %1;"
                     :: "r"(sCtl), "r"(128) : "memory");
        asm volatile("tcgen05.relinquish_alloc_permit.cta_group::1.sync.aligned;");
    }
    if (tid == 0)
        asm volatile("mbarrier.init.shared.b64 [%0], %1;" :: "r"(sCtl + 8), "r"(1) : "memory");
    __syncthreads();
    unsigned tmem;
    asm volatile("ld.shared.b32 %0, [%1];" : "=r"(tmem) : "r"(sCtl));

    // stage A (Wcat) and B (xp rows) into blocked-atom SW128 layout:
    // byte = (atom_row + atom_col*16)*1024 + inner_row*128 + (k'&31)*4
    const float* xpn = g_xp + ((unsigned)(n * VP + v0) * T_ + l) * CIN;
    for (int i = tid; i < 128 * 24; i += 256) {
        int row = i / 24, kq = (i % 24) * 4;
        unsigned off = SW128(((row >> 3) + (kq >> 5) * 16) * 1024 + (row & 7) * 128 + (kq & 31) * 4);
        *(float4*)(pA + off) = *(const float4*)&g_Wcat[row * 96 + kq];
        *(float4*)(pB + off) = *(const float4*)&xpn[row * (T_ * CIN) + kq];
    }
    asm volatile("fence.proxy.async.shared::cta;" ::: "memory");
    __syncthreads();

    if (wid == 0 && elect_one()) {
        const unsigned idesc = (1u << 4) | (2u << 7) | (2u << 10) | (16u << 17) | (8u << 24);
        unsigned long long adesc0 = DESC_BASE | ((unsigned long long)(sA >> 4) & 0x3FFF);
        unsigned long long bdesc0 = DESC_BASE | ((unsigned long long)(sB >> 4) & 0x3FFF);
#pragma unroll
        for (int s = 0; s < 12; s++) {     // K=96, 8 per step; 4 steps per 128B atom-col
            unsigned long long d = (unsigned long long)((s >> 2) * 1024 + (s & 3) * 2);
            mma_tf32_ss(tmem, adesc0 + d, bdesc0 + d, idesc, s > 0 ? 1u : 0u);
        }
        asm volatile(
            "tcgen05.commit.cta_group::1.mbarrier::arrive::one.shared::cluster.b64 [%0];"
            :: "r"(sCtl + 8) : "memory");
    }
    mbar_wait_parity(sCtl + 8, 0);
    asm volatile("tcgen05.fence::after_thread_sync;" ::: "memory");

    // warps 0-2 pull conv1/2/3 rows from TMEM into smem stage
    if (wid < 3) {
#pragma unroll
        for (int g = 0; g < 4; g++) {
            unsigned r[32];
            ldtm_x32(r, tmem + g * 32);
            asm volatile("tcgen05.wait::ld.sync.aligned;" ::: "memory");
            float* dst = sC + (wid * 32 + lid) * 132 + g * 32;
#pragma unroll
            for (int q = 0; q < 32; q++) dst[q] = __uint_as_float(r[q]);
        }
    }
    __syncthreads();

    // combine + gate + write (coalesced in v)
    for (int i = tid; i < 32 * 128; i += 256) {
        int c = i >> 7, vv = i & 127;
        if (vv < nv) {
            float t1 = sC[c * 132 + vv]         + b1[c];
            float t2 = sC[(32 + c) * 132 + vv]  + b2[c];
            float t3 = sC[(64 + c) * 132 + vv]  + b3[c];
            float r = t1 + 1.f / (1.f + __expf(-t2)) + t3;
            r = fmaxf(r, 0.f);
            int idx = ((n * CIN + c) * LP + l) * VP + v0 + vv;
            g_xt [idx] = r;
            g_xtb[idx] = __float2bfloat16(r);
        }
    }
    __syncthreads();
    if (tid == 0)
        asm volatile("mbarrier.inval.shared.b64 [%0];" :: "r"(sCtl + 8) : "memory");
    if (wid == 0)
        asm volatile("tcgen05.dealloc.cta_group::1.sync.aligned.b32 %0, %1;"
                     :: "r"(tmem), "r"(128));
#else
    // SIMT fallback (correctness only)
    for (int i = tid; i < 32 * 128; i += 256) {
        int c = i >> 7, vv = i & 127;
        if (vv < nv) {
            float a1 = 0.f, a2 = 0.f, a3 = 0.f;
            const float* xrow = g_xp + ((unsigned)(n * VP + v0 + vv) * T_ + l) * CIN;
            for (int kp = 0; kp < 96; kp++) {
                float xv = xrow[kp];
                a1 = fmaf(g_Wcat[c * 96 + kp], xv, a1);
                a2 = fmaf(g_Wcat[(32 + c) * 96 + kp], xv, a2);
                a3 = fmaf(g_Wcat[(64 + c) * 96 + kp], xv, a3);
            }
            float r = (a1 + b1[c]) + 1.f / (1.f + __expf(-(a2 + b2[c]))) + (a3 + b3[c]);
            r = fmaxf(r, 0.f);
            int idx = ((n * CIN + c) * LP + l) * VP + v0 + vv;
            g_xt [idx] = r;
            g_xtb[idx] = __float2bfloat16(r);
        }
    }
#endif
}

// ---------------------------------------------------------------------------
// Kernel C: diffusion GEMM, 128x128 tile, K = 512, bf16 tcgen05 w/ reg prefetch.
// grid (24, 8, 32): x = m-tile, y = mat*4 + w-tile, z = n.  256 threads.
// ---------------------------------------------------------------------------
#define C_SMEM_BYTES (1024 + 2 * 16384 + 64)

#if HAS_TCGEN05
#define KC_BOUNDS __launch_bounds__(256, 2)
#else
#define KC_BOUNDS __launch_bounds__(256, 1)
#endif

__global__ KC_BOUNDS void kernelC() {
    extern __shared__ char smem[];
    __shared__ int rowbase[128];
    __shared__ int obase[128];

    int tid = threadIdx.x, wid = tid >> 5, lid = tid & 31;
    int m0  = blockIdx.x * 128;
    int mat = blockIdx.y >> 2;
    int w0  = (blockIdx.y & 3) * 128;
    int n   = blockIdx.z;

    if (tid < 128) {
        int m = m0 + tid;
        bool valid = m < CIN * L_;
        int mm = valid ? m : 0;
        int c = mm / L_, l = mm % L_;
        rowbase[tid] = ((n * CIN + c) * LP + l) * VP;
        obase[tid]   = valid ? ((((mat * N_ + n) * CIN + c) * L_ + l) * VP) : -1;
    }

#if HAS_TCGEN05
    unsigned s0 = smem_u32(smem);
    unsigned sA = (s0 + 1023) & ~1023u;
    unsigned sB = sA + 16384;
    unsigned sCtl = sA + 32768;
    char* pA = smem + (sA - s0);
    char* pB = smem + (sB - s0);
    const __nv_bfloat16* __restrict__ Bm = mat ? g_A2Tb : g_ATb;

    if (wid == 0) {
        asm volatile("tcgen05.alloc.cta_group::1.sync.aligned.shared::cta.b32 [%0], %1;"
                     :: "r"(sCtl), "r"(128) : "memory");
        asm volatile("tcgen05.relinquish_alloc_permit.cta_group::1.sync.aligned;");
    }
    if (tid == 0)
        asm volatile("mbarrier.init.shared.b64 [%0], %1;" :: "r"(sCtl + 8), "r"(1) : "memory");
    __syncthreads();
    unsigned tmem;
    asm volatile("ld.shared.b32 %0, [%1];" : "=r"(tmem) : "r"(sCtl));

    const unsigned idesc = 0x490u | (16u << 17) | (8u << 24);
    unsigned long long adesc0 = DESC_BASE | ((unsigned long long)(sA >> 4) & 0x3FFF);
    unsigned long long bdesc0 = DESC_BASE | ((unsigned long long)(sB >> 4) & 0x3FFF);

    // per-thread load slots (fixed across K-chunks)
    const __nv_bfloat16* pa4[4];
    const __nv_bfloat16* pb4[4];
    unsigned swo[4];
#pragma unroll
    for (int it = 0; it < 4; it++) {
        int idx = tid + it * 256;
        int row = idx >> 3, c16 = idx & 7;
        swo[it] = SW128((unsigned)(row * 128 + c16 * 16));
        pa4[it] = &g_xtb[rowbase[row] + c16 * 8];
        pb4[it] = &Bm[(w0 + row) * VP + c16 * 8];
    }
    float4 va[4], vb[4];
#pragma unroll
    for (int it = 0; it < 4; it++) {
        va[it] = *(const float4*)pa4[it];
        vb[it] = *(const float4*)pb4[it];
    }

    for (int kc = 0; kc < 8; kc++) {
#pragma unroll
        for (int it = 0; it < 4; it++) {
            *(float4*)(pA + swo[it]) = va[it];
            *(float4*)(pB + swo[it]) = vb[it];
        }
        asm volatile("fence.proxy.async.shared::cta;" ::: "memory");
        __syncthreads();
        if (wid == 0 && elect_one()) {
#pragma unroll
            for (int j = 0; j < 4; j++) {
                mma_bf16_ss(tmem, adesc0 + j * 2, bdesc0 + j * 2, idesc,
                            (kc > 0 || j > 0) ? 1u : 0u);
            }
            asm volatile(
                "tcgen05.commit.cta_group::1.mbarrier::arrive::one.shared::cluster.b64 [%0];"
                :: "r"(sCtl + 8) : "memory");
        }
        if (kc < 7) {
            int k1 = (kc + 1) * 64;
#pragma unroll
            for (int it = 0; it < 4; it++) {
                va[it] = *(const float4*)(pa4[it] + k1);
                vb[it] = *(const float4*)(pb4[it] + k1);
            }
        }
        mbar_wait_parity(sCtl + 8, (unsigned)(kc & 1));
    }

    asm volatile("tcgen05.fence::after_thread_sync;" ::: "memory");

    if (wid < 4) {
        int row = wid * 32 + lid;
        int ob = obase[row];
#pragma unroll
        for (int g = 0; g < 4; g++) {
            unsigned r[32];
            ldtm_x32(r, tmem + g * 32);
            asm volatile("tcgen05.wait::ld.sync.aligned;" ::: "memory");
            if (ob >= 0) {
#pragma unroll
                for (int q = 0; q < 8; q++) {
                    float4 o = make_float4(__uint_as_float(r[q * 4 + 0]),
                                           __uint_as_float(r[q * 4 + 1]),
                                           __uint_as_float(r[q * 4 + 2]),
                                           __uint_as_float(r[q * 4 + 3]));
                    *(float4*)&g_x12[ob + w0 + g * 32 + q * 4] = o;
                }
            }
        }
    }
    __syncthreads();
    if (tid == 0)
        asm volatile("mbarrier.inval.shared.b64 [%0];" :: "r"(sCtl + 8) : "memory");
    if (wid == 0)
        asm volatile("tcgen05.dealloc.cta_group::1.sync.aligned.b32 %0, %1;"
                     :: "r"(tmem), "r"(128));

#else
    // SIMT fp32 fallback: 128x128 tile, 8x8 micro
    (void)wid; (void)lid;
    float* As = (float*)smem;
    float* Bs = As + 16 * 132;
    const float* __restrict__ Bmf = mat ? g_A2pad : g_Apad;
    __syncthreads();

    int ty = tid >> 4, tx = tid & 15;
    float acc[8][8] = {};

    for (int k0 = 0; k0 < VP; k0 += 16) {
        __syncthreads();
#pragma unroll
        for (int it = 0; it < 2; it++) {
            int i = tid + it * 256;
            int arow = i >> 2, aq = i & 3;
            float4 va2 = *(const float4*)&g_xt[rowbase[arow] + k0 + aq * 4];
            As[(aq * 4 + 0) * 132 + arow] = va2.x;
            As[(aq * 4 + 1) * 132 + arow] = va2.y;
            As[(aq * 4 + 2) * 132 + arow] = va2.z;
            As[(aq * 4 + 3) * 132 + arow] = va2.w;
            int bk = i >> 5, bw = (i & 31) * 4;
            float4 vb2 = *(const float4*)&Bmf[(k0 + bk) * VP + w0 + bw];
            *(float4*)&Bs[bk * 132 + bw] = vb2;
        }
        __syncthreads();
#pragma unroll
        for (int kk = 0; kk < 16; kk++) {
            float4 a0 = *(const float4*)&As[kk * 132 + ty * 8];
            float4 a1 = *(const float4*)&As[kk * 132 + ty * 8 + 4];
            float4 b0 = *(const float4*)&Bs[kk * 132 + tx * 8];
            float4 b1v = *(const float4*)&Bs[kk * 132 + tx * 8 + 4];
            float ar[8] = {a0.x, a0.y, a0.z, a0.w, a1.x, a1.y, a1.z, a1.w};
            float br[8] = {b0.x, b0.y, b0.z, b0.w, b1v.x, b1v.y, b1v.z, b1v.w};
#pragma unroll
            for (int i = 0; i < 8; i++)
#pragma unroll
                for (int j = 0; j < 8; j++)
                    acc[i][j] = fmaf(ar[i], br[j], acc[i][j]);
        }
    }
#pragma unroll
    for (int i = 0; i < 8; i++) {
        int ob = obase[ty * 8 + i];
        if (ob >= 0) {
            *(float4*)&g_x12[ob + w0 + tx * 8]     = make_float4(acc[i][0], acc[i][1], acc[i][2], acc[i][3]);
            *(float4*)&g_x12[ob + w0 + tx * 8 + 4] = make_float4(acc[i][4], acc[i][5], acc[i][6], acc[i][7]);
        }
    }
#endif
}

// ---------------------------------------------------------------------------
// Kernel D: 1x1 projection (K=96) + bias + PReLU, write NCHW output.
// grid (16, 24, 32), 256 threads.
// ---------------------------------------------------------------------------
__global__ __launch_bounds__(256) void kernelD(
    const float* __restrict__ bout,
    const float* __restrict__ pa,
    float* __restrict__ out)
{
    __shared__ __align__(16) float Xs[96][128];

    int n  = blockIdx.z;
    int w0 = blockIdx.x * 32;
    int l0 = blockIdx.y * 4;
    int tid = threadIdx.x;

    for (int idx = tid; idx < 96 * 128; idx += 256) {
        int r   = idx >> 7;
        int rem = idx & 127;
        int li  = rem >> 5;
        int wi  = rem & 31;
        int hop = r >> 5, c = r & 31;
        int l = l0 + li, w = w0 + wi;
        float val = 0.f;
        if (l < L_) {
            if (hop == 0)
                val = g_xt[((n * CIN + c) * LP + l) * VP + w];
            else
                val = g_x12[((((hop - 1) * N_ + n) * CIN + c) * L_ + l) * VP + w];
        }
        Xs[r][wi * 4 + li] = val;
    }
    __syncthreads();

    int to = tid & 15;
    int tj = tid >> 4;
    float acc[4][8] = {};
#pragma unroll 4
    for (int k = 0; k < 96; k++) {
        float4 wv = *(const float4*)&g_Wt[k * 64 + to * 4];
#pragma unroll
        for (int jj = 0; jj < 8; jj++) {
            float xv = Xs[k][tj * 8 + jj];
            acc[0][jj] = fmaf(wv.x, xv, acc[0][jj]);
            acc[1][jj] = fmaf(wv.y, xv, acc[1][jj]);
            acc[2][jj] = fmaf(wv.z, xv, acc[2][jj]);
            acc[3][jj] = fmaf(wv.w, xv, acc[3][jj]);
        }
    }
    float a = pa[0];
#pragma unroll
    for (int i = 0; i < 4; i++) {
        int o = to * 4 + i;
        float b = bout[o];
#pragma unroll
        for (int jj = 0; jj < 8; jj++) {
            int j  = tj * 8 + jj;
            int wi = j >> 2, li = j & 3;
            int w = w0 + wi, l = l0 + li;
            if (w < V_ && l < L_) {
                float vv = acc[i][jj] + b;
                out[((n * COUT + o) * V_ + w) * L_ + l] = vv > 0.f ? vv : a * vv;
            }
        }
    }
}

// ---------------------------------------------------------------------------
extern "C" void kernel_launch(void* const* d_in, const int* in_sizes, int n_in,
                              void* d_out, int out_size) {
    const float* x    = (const float*)d_in[0];
    const float* A    = (const float*)d_in[1];
    const float* w1   = (const float*)d_in[2];
    const float* b1   = (const float*)d_in[3];
    const float* w2   = (const float*)d_in[4];
    const float* b2   = (const float*)d_in[5];
    const float* w3   = (const float*)d_in[6];
    const float* b3   = (const float*)d_in[7];
    const float* wout = (const float*)d_in[8];
    const float* bout = (const float*)d_in[9];
    const float* pa   = (const float*)d_in[10];
    float* out = (float*)d_out;

    cudaFuncSetAttribute(kernelC,     cudaFuncAttributeMaxDynamicSharedMemorySize, C_SMEM_BYTES);
    cudaFuncSetAttribute(kernelB_mma, cudaFuncAttributeMaxDynamicSharedMemorySize, BM_SMEM);
    cudaFuncSetAttribute(kernelX,     cudaFuncAttributeMaxDynamicSharedMemorySize, X_SMEM);

    kernelA<<<dim3(32, 32), dim3(16, 16)>>>(A);
    kernelE<<<24, 256>>>(wout);
    kernelW<<<48, 256>>>(w1, w2, w3);
    kernelX<<<dim3(125, 32), 256, X_SMEM>>>(x);
    kernelB_mma<<<dim3(4, 94, 32), 256, BM_SMEM>>>(b1, b2, b3);
    kernelC<<<dim3(24, 8, 32), 256, C_SMEM_BYTES>>>();
    kernelD<<<dim3(16, 24, 32), 256>>>(bout, pa, out);
}

// round 5
// speedup vs baseline: 2.8578x; 1.2692x over previous
#include <cuda_runtime.h>
#include <cuda_bf16.h>

#define N_    32
#define CIN   32
#define V_    500
#define T_    96
#define L_    94      // T - K + 1
#define COUT  64
#define VP    512     // padded v/w dim
#define LP    96      // padded l dim in g_xt

// Scratch (zero-initialized at module load; padding regions never written)
__device__ float          g_xt  [N_ * CIN * LP * VP];     // [n][c][l][v] fp32
__device__ __nv_bfloat16  g_xtb [N_ * CIN * LP * VP];     // bf16 copy
__device__ float          g_x12 [2 * N_ * CIN * L_ * VP]; // [mat][n][c][l][w]
__device__ float          g_Apad [VP * VP];               // fallback
__device__ float          g_A2pad[VP * VP];               // fallback
__device__ __nv_bfloat16  g_ATb [VP * VP];                // A^T
__device__ __nv_bfloat16  g_A2Tb[VP * VP];                // (A@A)^T
__device__ float          g_Wt  [96 * 64];                // fallback proj weights
// xp, pre-swizzled: [n][vc=4][t=96] blocks of 4096 floats; elem (vr,ci) at SW128(vr*128+ci*4)
__device__ float          g_xpsw[N_ * 4 * T_ * 4096];
__device__ float          g_Wcat[128 * 96];               // stacked conv weights (tf32)

#define HAS_TCGEN05 (defined(__CUDA_ARCH_FEAT_SM103_ALL) || defined(__CUDA_ARCH_FEAT_SM100_ALL) || defined(__CUDA_ARCH_FEAT_SM101_ALL))

#define SW128(o) ((o) ^ (((o) >> 3) & 0x70))

static __device__ __forceinline__ unsigned smem_u32(const void* p) {
    unsigned a;
    asm("{ .reg .u64 t; cvta.to.shared.u64 t, %1; cvt.u32.u64 %0, t; }"
        : "=r"(a) : "l"(p));
    return a;
}

static __device__ __forceinline__ float tf32r(float x) {
    float r;
    asm("cvt.rna.tf32.f32 %0, %1;" : "=f"(r) : "f"(x));
    return r;
}

#if HAS_TCGEN05
static __device__ __forceinline__ unsigned elect_one() {
    unsigned p;
    asm volatile("{\n\t.reg .pred p;\n\telect.sync _|p, 0xFFFFFFFF;\n\t"
                 "selp.b32 %0, 1, 0, p;\n\t}" : "=r"(p));
    return p;
}

static __device__ __forceinline__ void mbar_wait_parity(unsigned mbar, unsigned phase) {
    asm volatile(
        "{\n\t.reg .pred P1;\n\t"
        "WL_%=:\n\t"
        "mbarrier.try_wait.parity.acquire.cta.shared::cta.b64 P1, [%0], %1, 0x989680;\n\t"
        "@P1 bra.uni WD_%=;\n\t"
        "bra.uni WL_%=;\n\t"
        "WD_%=:\n\t}"
        :: "r"(mbar), "r"(phase) : "memory");
}

static __device__ __forceinline__ void mma_bf16_ss(unsigned d_tmem, unsigned long long a_desc,
                                                   unsigned long long b_desc, unsigned idesc,
                                                   unsigned en) {
    asm volatile(
        "{\n\t.reg .pred p;\n\t"
        "setp.ne.u32 p, %4, 0;\n\t"
        "tcgen05.mma.cta_group::1.kind::f16 [%0], %1, %2, %3, {%5, %5, %5, %5}, p;\n\t}"
        :: "r"(d_tmem), "l"(a_desc), "l"(b_desc), "r"(idesc), "r"(en), "r"(0u)
        : "memory");
}

static __device__ __forceinline__ void mma_tf32_ss(unsigned d_tmem, unsigned long long a_desc,
                                                   unsigned long long b_desc, unsigned idesc,
                                                   unsigned en) {
    asm volatile(
        "{\n\t.reg .pred p;\n\t"
        "setp.ne.u32 p, %4, 0;\n\t"
        "tcgen05.mma.cta_group::1.kind::tf32 [%0], %1, %2, %3, {%5, %5, %5, %5}, p;\n\t}"
        :: "r"(d_tmem), "l"(a_desc), "l"(b_desc), "r"(idesc), "r"(en), "r"(0u)
        : "memory");
}

static __device__ __forceinline__ void ldtm_x32(unsigned* r, unsigned addr) {
    asm volatile(
        "tcgen05.ld.sync.aligned.32x32b.x32.b32 "
        "{%0, %1, %2, %3, %4, %5, %6, %7, "
        " %8, %9, %10, %11, %12, %13, %14, %15, "
        " %16, %17, %18, %19, %20, %21, %22, %23, "
        " %24, %25, %26, %27, %28, %29, %30, %31}, [%32];"
        : "=r"(r[0]),  "=r"(r[1]),  "=r"(r[2]),  "=r"(r[3]),
          "=r"(r[4]),  "=r"(r[5]),  "=r"(r[6]),  "=r"(r[7]),
          "=r"(r[8]),  "=r"(r[9]),  "=r"(r[10]), "=r"(r[11]),
          "=r"(r[12]), "=r"(r[13]), "=r"(r[14]), "=r"(r[15]),
          "=r"(r[16]), "=r"(r[17]), "=r"(r[18]), "=r"(r[19]),
          "=r"(r[20]), "=r"(r[21]), "=r"(r[22]), "=r"(r[23]),
          "=r"(r[24]), "=r"(r[25]), "=r"(r[26]), "=r"(r[27]),
          "=r"(r[28]), "=r"(r[29]), "=r"(r[30]), "=r"(r[31])
        : "r"(addr));
}

#define DESC_BASE ((2ULL << 61) | (1ULL << 46) | (64ULL << 32) | (1ULL << 16))
#endif  // HAS_TCGEN05

// ---------------------------------------------------------------------------
// Kernel A: A@A; emit fp32 padded (fallback) + bf16 transposed
// ---------------------------------------------------------------------------
__global__ __launch_bounds__(256) void kernelA(const float* __restrict__ A) {
    __shared__ float As[16][16];
    __shared__ float Bs[16][16];
    int tx = threadIdx.x, ty = threadIdx.y;
    int w = blockIdx.x * 16 + tx;
    int v = blockIdx.y * 16 + ty;
    float aval = (v < V_ && w < V_) ? A[v * V_ + w] : 0.f;
    float acc = 0.f;
    for (int u0 = 0; u0 < V_; u0 += 16) {
        int u1 = u0 + tx, u2 = u0 + ty;
        As[ty][tx] = (v < V_ && u1 < V_) ? A[v * V_ + u1] : 0.f;
        Bs[ty][tx] = (u2 < V_ && w < V_) ? A[u2 * V_ + w] : 0.f;
        __syncthreads();
#pragma unroll
        for (int u = 0; u < 16; u++) acc += As[ty][u] * Bs[u][tx];
        __syncthreads();
    }
    float a2val = (v < V_ && w < V_) ? acc : 0.f;
    g_Apad [v * VP + w] = aval;
    g_A2pad[v * VP + w] = a2val;
    g_ATb [w * VP + v] = __float2bfloat16(aval);
    g_A2Tb[w * VP + v] = __float2bfloat16(a2val);
}

__global__ __launch_bounds__(256) void kernelE(const float* __restrict__ wout) {
    int idx = blockIdx.x * 256 + threadIdx.x;
    if (idx < 96 * 64) {
        int o = idx / 96, k = idx % 96;
        g_Wt[k * 64 + o] = wout[idx];
    }
}

// ---------------------------------------------------------------------------
// Kernel W: g_Wcat[row][kk*32+ci]; rows 0-31/32-63/64-95 = conv1/2/3, rest 0
// ---------------------------------------------------------------------------
__global__ __launch_bounds__(256) void kernelW(
    const float* __restrict__ w1, const float* __restrict__ w2,
    const float* __restrict__ w3)
{
    int idx = blockIdx.x * 256 + threadIdx.x;
    if (idx < 128 * 96) {
        int row = idx / 96, kp = idx % 96;
        int kk = kp >> 5, ci = kp & 31;
        float val = 0.f;
        if (row < 32)       val = w1[row * 96 + ci * 3 + kk];
        else if (row < 64)  val = w2[(row - 32) * 96 + ci * 3 + kk];
        else if (row < 96)  val = w3[(row - 64) * 96 + ci * 3 + kk];
        g_Wcat[idx] = tf32r(val);
    }
}

// ---------------------------------------------------------------------------
// Kernel X: x[n][ci][v][t] -> g_xpsw swizzled atom-col blocks (tf32-rounded)
// grid (125, 32), 4 v per block
// ---------------------------------------------------------------------------
#define X_SMEM (4 * 96 * 33 * 4)
__global__ __launch_bounds__(256) void kernelX(const float* __restrict__ x) {
    extern __shared__ float xs[];          // [vi][t][33]
    int v0 = blockIdx.x * 4, n = blockIdx.y;
    int tid = threadIdx.x;
    for (int i = tid; i < CIN * 4 * T_; i += 256) {
        int t  = i % T_;
        int r  = i / T_;
        int vi = r & 3;
        int ci = r >> 2;
        xs[(vi * T_ + t) * 33 + ci] = x[((n * CIN + ci) * V_ + v0 + vi) * T_ + t];
    }
    __syncthreads();
    for (int i = tid; i < 4 * T_ * CIN; i += 256) {
        int ci = i & 31;
        int r  = i >> 5;
        int t  = r % T_;
        int vi = r / T_;
        int v = v0 + vi, vc = v >> 7, vr = v & 127;
        g_xpsw[((size_t)(n * 4 + vc) * T_ + t) * 4096 + (SW128(vr * 128 + ci * 4) >> 2)]
            = tf32r(xs[(vi * T_ + t) * 33 + ci]);
    }
}

// ---------------------------------------------------------------------------
// Kernel B (tcgen05 tf32): per CTA (vc, n) — ALL 94 l's, t-col ring, 4-l TMEM
// batches.  A = xp (M=128 v), B = Wcat (N=128 conv rows), K window 3 t-cols.
// grid (4, 32), 256 threads.
// ---------------------------------------------------------------------------
#define BRING 8
#define BM_SMEM (1024 + 49152 + BRING * 16384 + 64)

__global__ __launch_bounds__(256) void kernelB_mma(
    const float* __restrict__ b1, const float* __restrict__ b2,
    const float* __restrict__ b3)
{
    int tid = threadIdx.x, wid = tid >> 5;
    int vc = blockIdx.x, n = blockIdx.y;
    int v0 = vc * 128;
    __shared__ float sb[96];
    if (tid < 96) sb[tid] = (tid < 32) ? b1[tid] : (tid < 64) ? b2[tid - 32] : b3[tid - 64];

#if HAS_TCGEN05
    extern __shared__ char smem[];
    unsigned s0 = smem_u32(smem);
    unsigned sW = (s0 + 1023) & ~1023u;
    unsigned sR = sW + 49152;
    unsigned sCtl = sR + BRING * 16384;
    char* pW = smem + (sW - s0);
    char* pR = smem + (sR - s0);

    if (wid == 0) {
        asm volatile("tcgen05.alloc.cta_group::1.sync.aligned.shared::cta.b32 [%0], %1;"
                     :: "r"(sCtl), "r"(512) : "memory");
        asm volatile("tcgen05.relinquish_alloc_permit.cta_group::1.sync.aligned;");
    }
    if (tid == 0)
        asm volatile("mbarrier.init.shared.b64 [%0], %1;" :: "r"(sCtl + 8), "r"(1) : "memory");

    // stage Wcat (B-tile, 128 rows x 96 k, 3 atom-cols)
    for (int i = tid; i < 128 * 24; i += 256) {
        int row = i / 24, kq = (i % 24) * 4;
        unsigned off = (kq >> 5) * 16384 + (row >> 3) * 1024 + SW128((row & 7) * 128 + (kq & 31) * 4);
        *(float4*)(pW + off) = *(const float4*)&g_Wcat[row * 96 + kq];
    }
    asm volatile("fence.proxy.async.shared::cta;" ::: "memory");
    __syncthreads();
    unsigned tmem;
    asm volatile("ld.shared.b32 %0, [%1];" : "=r"(tmem) : "r"(sCtl));

    const unsigned idesc = (1u << 4) | (2u << 7) | (2u << 10) | (16u << 17) | (8u << 24);
    unsigned long long wdesc = DESC_BASE | ((unsigned long long)(sW >> 4) & 0x3FFF);
    unsigned long long rdesc = DESC_BASE | ((unsigned long long)(sR >> 4) & 0x3FFF);

    const float* xbase = g_xpsw + (size_t)(n * 4 + vc) * T_ * 4096;
    int staged = 0;

    for (int lb = 0; lb < 24; lb++) {
        int tend = lb * 4 + 6; if (tend > 96) tend = 96;
        for (; staged < tend; staged++) {
            const float4* src = (const float4*)(xbase + (size_t)staged * 4096);
            float4* dst = (float4*)(pR + (staged & (BRING - 1)) * 16384);
            for (int j = tid; j < 1024; j += 256) dst[j] = src[j];
        }
        asm volatile("fence.proxy.async.shared::cta;" ::: "memory");
        __syncthreads();

        if (wid == 0 && elect_one()) {
            asm volatile("tcgen05.fence::after_thread_sync;" ::: "memory");
#pragma unroll
            for (int ls = 0; ls < 4; ls++) {
                int l = lb * 4 + ls;
                if (l < 94) {
#pragma unroll
                    for (int s = 0; s < 12; s++) {
                        unsigned long long ad = rdesc +
                            (unsigned long long)(((l + (s >> 2)) & (BRING - 1)) * 1024 + (s & 3) * 2);
                        unsigned long long bd = wdesc +
                            (unsigned long long)((s >> 2) * 1024 + (s & 3) * 2);
                        mma_tf32_ss(tmem + ls * 128, ad, bd, idesc, s > 0 ? 1u : 0u);
                    }
                }
            }
            asm volatile(
                "tcgen05.commit.cta_group::1.mbarrier::arrive::one.shared::cluster.b64 [%0];"
                :: "r"(sCtl + 8) : "memory");
        }
        mbar_wait_parity(sCtl + 8, (unsigned)(lb & 1));
        asm volatile("tcgen05.fence::after_thread_sync;" ::: "memory");

        if (tid < 128) {
            int v = v0 + tid;
            for (int ls = 0; ls < 4; ls++) {
                int l = lb * 4 + ls;
                if (l >= 94) break;
                unsigned q[96];
                ldtm_x32(q,      tmem + ls * 128);
                ldtm_x32(q + 32, tmem + ls * 128 + 32);
                ldtm_x32(q + 64, tmem + ls * 128 + 64);
                asm volatile("tcgen05.wait::ld.sync.aligned;" ::: "memory");
                if (v < V_) {
#pragma unroll
                    for (int c = 0; c < 32; c++) {
                        float t1 = __uint_as_float(q[c])      + sb[c];
                        float t2 = __uint_as_float(q[32 + c]) + sb[32 + c];
                        float t3 = __uint_as_float(q[64 + c]) + sb[64 + c];
                        float r = t1 + 1.f / (1.f + __expf(-t2)) + t3;
                        r = fmaxf(r, 0.f);
                        int idx = ((n * CIN + c) * LP + l) * VP + v;
                        g_xt [idx] = r;
                        g_xtb[idx] = __float2bfloat16(r);
                    }
                }
            }
            asm volatile("tcgen05.fence::before_thread_sync;" ::: "memory");
        }
        __syncthreads();
    }
    if (wid == 0)
        asm volatile("tcgen05.dealloc.cta_group::1.sync.aligned.b32 %0, %1;"
                     :: "r"(tmem), "r"(512));
    if (tid == 0)
        asm volatile("mbarrier.inval.shared.b64 [%0];" :: "r"(sCtl + 8) : "memory");
#else
    __syncthreads();
    for (int i = tid; i < 94 * 32 * 128; i += 256) {
        int l = i / (32 * 128);
        int r = i % (32 * 128);
        int c = r >> 7, vi = r & 127;
        int v = v0 + vi;
        if (v < V_) {
            float a1 = 0.f, a2 = 0.f, a3 = 0.f;
            for (int k = 0; k < 96; k++) {
                int kk = k >> 5, ci = k & 31;
                float xv = g_xpsw[((size_t)(n * 4 + vc) * T_ + l + kk) * 4096
                                  + (SW128(vi * 128 + ci * 4) >> 2)];
                a1 = fmaf(g_Wcat[c * 96 + k], xv, a1);
                a2 = fmaf(g_Wcat[(32 + c) * 96 + k], xv, a2);
                a3 = fmaf(g_Wcat[(64 + c) * 96 + k], xv, a3);
            }
            float r2 = (a1 + sb[c]) + 1.f / (1.f + __expf(-(a2 + sb[32 + c]))) + (a3 + sb[64 + c]);
            r2 = fmaxf(r2, 0.f);
            int idx = ((n * CIN + c) * LP + l) * VP + v;
            g_xt [idx] = r2;
            g_xtb[idx] = __float2bfloat16(r2);
        }
    }
#endif
}

// ---------------------------------------------------------------------------
// Kernel C: diffusion GEMM (unchanged from R4) — bf16 tcgen05, reg prefetch
// grid (24, 8, 32), 256 threads.
// ---------------------------------------------------------------------------
#define C_SMEM_BYTES (1024 + 2 * 16384 + 64)

#if HAS_TCGEN05
#define KC_BOUNDS __launch_bounds__(256, 2)
#else
#define KC_BOUNDS __launch_bounds__(256, 1)
#endif

__global__ KC_BOUNDS void kernelC() {
    extern __shared__ char smem[];
    __shared__ int rowbase[128];
    __shared__ int obase[128];

    int tid = threadIdx.x, wid = tid >> 5, lid = tid & 31;
    int m0  = blockIdx.x * 128;
    int mat = blockIdx.y >> 2;
    int w0  = (blockIdx.y & 3) * 128;
    int n   = blockIdx.z;

    if (tid < 128) {
        int m = m0 + tid;
        bool valid = m < CIN * L_;
        int mm = valid ? m : 0;
        int c = mm / L_, l = mm % L_;
        rowbase[tid] = ((n * CIN + c) * LP + l) * VP;
        obase[tid]   = valid ? ((((mat * N_ + n) * CIN + c) * L_ + l) * VP) : -1;
    }

#if HAS_TCGEN05
    unsigned s0 = smem_u32(smem);
    unsigned sA = (s0 + 1023) & ~1023u;
    unsigned sB = sA + 16384;
    unsigned sCtl = sA + 32768;
    char* pA = smem + (sA - s0);
    char* pB = smem + (sB - s0);
    const __nv_bfloat16* __restrict__ Bm = mat ? g_A2Tb : g_ATb;

    if (wid == 0) {
        asm volatile("tcgen05.alloc.cta_group::1.sync.aligned.shared::cta.b32 [%0], %1;"
                     :: "r"(sCtl), "r"(128) : "memory");
        asm volatile("tcgen05.relinquish_alloc_permit.cta_group::1.sync.aligned;");
    }
    if (tid == 0)
        asm volatile("mbarrier.init.shared.b64 [%0], %1;" :: "r"(sCtl + 8), "r"(1) : "memory");
    __syncthreads();
    unsigned tmem;
    asm volatile("ld.shared.b32 %0, [%1];" : "=r"(tmem) : "r"(sCtl));

    const unsigned idesc = 0x490u | (16u << 17) | (8u << 24);
    unsigned long long adesc0 = DESC_BASE | ((unsigned long long)(sA >> 4) & 0x3FFF);
    unsigned long long bdesc0 = DESC_BASE | ((unsigned long long)(sB >> 4) & 0x3FFF);

    const __nv_bfloat16* pa4[4];
    const __nv_bfloat16* pb4[4];
    unsigned swo[4];
#pragma unroll
    for (int it = 0; it < 4; it++) {
        int idx = tid + it * 256;
        int row = idx >> 3, c16 = idx & 7;
        swo[it] = SW128((unsigned)(row * 128 + c16 * 16));
        pa4[it] = &g_xtb[rowbase[row] + c16 * 8];
        pb4[it] = &Bm[(w0 + row) * VP + c16 * 8];
    }
    float4 va[4], vb[4];
#pragma unroll
    for (int it = 0; it < 4; it++) {
        va[it] = *(const float4*)pa4[it];
        vb[it] = *(const float4*)pb4[it];
    }

    for (int kc = 0; kc < 8; kc++) {
#pragma unroll
        for (int it = 0; it < 4; it++) {
            *(float4*)(pA + swo[it]) = va[it];
            *(float4*)(pB + swo[it]) = vb[it];
        }
        asm volatile("fence.proxy.async.shared::cta;" ::: "memory");
        __syncthreads();
        if (wid == 0 && elect_one()) {
#pragma unroll
            for (int j = 0; j < 4; j++) {
                mma_bf16_ss(tmem, adesc0 + j * 2, bdesc0 + j * 2, idesc,
                            (kc > 0 || j > 0) ? 1u : 0u);
            }
            asm volatile(
                "tcgen05.commit.cta_group::1.mbarrier::arrive::one.shared::cluster.b64 [%0];"
                :: "r"(sCtl + 8) : "memory");
        }
        if (kc < 7) {
            int k1 = (kc + 1) * 64;
#pragma unroll
            for (int it = 0; it < 4; it++) {
                va[it] = *(const float4*)(pa4[it] + k1);
                vb[it] = *(const float4*)(pb4[it] + k1);
            }
        }
        mbar_wait_parity(sCtl + 8, (unsigned)(kc & 1));
    }

    asm volatile("tcgen05.fence::after_thread_sync;" ::: "memory");

    if (wid < 4) {
        int row = wid * 32 + lid;
        int ob = obase[row];
#pragma unroll
        for (int g = 0; g < 4; g++) {
            unsigned r[32];
            ldtm_x32(r, tmem + g * 32);
            asm volatile("tcgen05.wait::ld.sync.aligned;" ::: "memory");
            if (ob >= 0) {
#pragma unroll
                for (int q = 0; q < 8; q++) {
                    float4 o = make_float4(__uint_as_float(r[q * 4 + 0]),
                                           __uint_as_float(r[q * 4 + 1]),
                                           __uint_as_float(r[q * 4 + 2]),
                                           __uint_as_float(r[q * 4 + 3]));
                    *(float4*)&g_x12[ob + w0 + g * 32 + q * 4] = o;
                }
            }
        }
    }
    __syncthreads();
    if (tid == 0)
        asm volatile("mbarrier.inval.shared.b64 [%0];" :: "r"(sCtl + 8) : "memory");
    if (wid == 0)
        asm volatile("tcgen05.dealloc.cta_group::1.sync.aligned.b32 %0, %1;"
                     :: "r"(tmem), "r"(128));
#else
    (void)wid; (void)lid;
    float* As = (float*)smem;
    float* Bs = As + 16 * 132;
    const float* __restrict__ Bmf = mat ? g_A2pad : g_Apad;
    __syncthreads();
    int ty = tid >> 4, tx = tid & 15;
    float acc[8][8] = {};
    for (int k0 = 0; k0 < VP; k0 += 16) {
        __syncthreads();
#pragma unroll
        for (int it = 0; it < 2; it++) {
            int i = tid + it * 256;
            int arow = i >> 2, aq = i & 3;
            float4 va2 = *(const float4*)&g_xt[rowbase[arow] + k0 + aq * 4];
            As[(aq * 4 + 0) * 132 + arow] = va2.x;
            As[(aq * 4 + 1) * 132 + arow] = va2.y;
            As[(aq * 4 + 2) * 132 + arow] = va2.z;
            As[(aq * 4 + 3) * 132 + arow] = va2.w;
            int bk = i >> 5, bw = (i & 31) * 4;
            float4 vb2 = *(const float4*)&Bmf[(k0 + bk) * VP + w0 + bw];
            *(float4*)&Bs[bk * 132 + bw] = vb2;
        }
        __syncthreads();
#pragma unroll
        for (int kk = 0; kk < 16; kk++) {
            float4 a0 = *(const float4*)&As[kk * 132 + ty * 8];
            float4 a1 = *(const float4*)&As[kk * 132 + ty * 8 + 4];
            float4 b0 = *(const float4*)&Bs[kk * 132 + tx * 8];
            float4 b1v = *(const float4*)&Bs[kk * 132 + tx * 8 + 4];
            float ar[8] = {a0.x, a0.y, a0.z, a0.w, a1.x, a1.y, a1.z, a1.w};
            float br[8] = {b0.x, b0.y, b0.z, b0.w, b1v.x, b1v.y, b1v.z, b1v.w};
#pragma unroll
            for (int i = 0; i < 8; i++)
#pragma unroll
                for (int j = 0; j < 8; j++)
                    acc[i][j] = fmaf(ar[i], br[j], acc[i][j]);
        }
    }
#pragma unroll
    for (int i = 0; i < 8; i++) {
        int ob = obase[ty * 8 + i];
        if (ob >= 0) {
            *(float4*)&g_x12[ob + w0 + tx * 8]     = make_float4(acc[i][0], acc[i][1], acc[i][2], acc[i][3]);
            *(float4*)&g_x12[ob + w0 + tx * 8 + 4] = make_float4(acc[i][4], acc[i][5], acc[i][6], acc[i][7]);
        }
    }
#endif
}

// ---------------------------------------------------------------------------
// Kernel D (tcgen05 tf32): projection + PReLU.
// Per CTA (wc, n): M rows = 16 w x 8 l, N = 64 o, K = 96 (hop,c).
// 12 l-batches x 8 w-subtiles (D = 64 cols each, 512 per batch).
// grid (4, 32), 256 threads.
// ---------------------------------------------------------------------------
#define D_SMEM (1024 + 24576 + 49152 + 64)

__global__ __launch_bounds__(256) void kernelD_mma(
    const float* __restrict__ wout,
    const float* __restrict__ bout,
    const float* __restrict__ pa,
    float* __restrict__ out)
{
    int tid = threadIdx.x, wid = tid >> 5;
    int wc = blockIdx.x, n = blockIdx.y;
    int w0 = wc * 128;
    __shared__ float sbo[64];
    __shared__ float spa;
    if (tid < 64) sbo[tid] = bout[tid];
    if (tid == 0) spa = pa[0];

#if HAS_TCGEN05
    extern __shared__ char smem[];
    unsigned s0 = smem_u32(smem);
    unsigned sWt = (s0 + 1023) & ~1023u;
    unsigned sA = sWt + 24576;
    unsigned sCtl = sA + 49152;
    char* pWt = smem + (sWt - s0);
    char* pA  = smem + (sA - s0);

    if (wid == 0) {
        asm volatile("tcgen05.alloc.cta_group::1.sync.aligned.shared::cta.b32 [%0], %1;"
                     :: "r"(sCtl), "r"(512) : "memory");
        asm volatile("tcgen05.relinquish_alloc_permit.cta_group::1.sync.aligned;");
    }
    if (tid == 0)
        asm volatile("mbarrier.init.shared.b64 [%0], %1;" :: "r"(sCtl + 8), "r"(1) : "memory");

    // stage w_out (B-tile: 64 rows x 96 k, rows natively K-major)
    for (int i = tid; i < 64 * 24; i += 256) {
        int row = i / 24, kq = (i % 24) * 4;
        unsigned off = (kq >> 5) * 8192 + (row >> 3) * 1024 + SW128((row & 7) * 128 + (kq & 31) * 4);
        float4 v = *(const float4*)&wout[row * 96 + kq];
        v.x = tf32r(v.x); v.y = tf32r(v.y); v.z = tf32r(v.z); v.w = tf32r(v.w);
        *(float4*)(pWt + off) = v;
    }
    asm volatile("fence.proxy.async.shared::cta;" ::: "memory");
    __syncthreads();
    unsigned tmem;
    asm volatile("ld.shared.b32 %0, [%1];" : "=r"(tmem) : "r"(sCtl));

    const unsigned idesc = (1u << 4) | (2u << 7) | (2u << 10) | (8u << 17) | (8u << 24);
    unsigned long long wdesc = DESC_BASE | ((unsigned long long)(sWt >> 4) & 0x3FFF);
    unsigned long long adesc = DESC_BASE | ((unsigned long long)(sA >> 4) & 0x3FFF);

    int cm = 0;
    for (int lb = 0; lb < 12; lb++) {
        for (int wq = 0; wq < 8; wq++) {
            // stage A: rows j = wsub*8 + lslot, K = 96 (hop,c), transpose from h
            for (int i = tid; i < 3072; i += 256) {
                int k = i >> 5, lslot = (i >> 2) & 7, wq4 = i & 3;
                int hop = k >> 5, c = k & 31;
                int l = lb * 8 + lslot;
                int lcl = l > 93 ? 93 : l;
                const float* src;
                if (hop == 0)
                    src = g_xt + ((size_t)(n * CIN + c) * LP + lcl) * VP + w0 + wq * 16 + wq4 * 4;
                else
                    src = g_x12 + ((size_t)(((hop - 1) * N_ + n) * CIN + c) * L_ + lcl) * VP
                          + w0 + wq * 16 + wq4 * 4;
                float4 v = *(const float4*)src;
                float vv[4] = {v.x, v.y, v.z, v.w};
#pragma unroll
                for (int m = 0; m < 4; m++) {
                    int wsub = wq4 * 4 + m;
                    unsigned off = (k >> 5) * 16384 + wsub * 1024 + SW128(lslot * 128 + (k & 31) * 4);
                    *(float*)(pA + off) = tf32r(vv[m]);
                }
            }
            asm volatile("fence.proxy.async.shared::cta;" ::: "memory");
            __syncthreads();
            if (wid == 0 && elect_one()) {
                asm volatile("tcgen05.fence::after_thread_sync;" ::: "memory");
#pragma unroll
                for (int s = 0; s < 12; s++) {
                    mma_tf32_ss(tmem + wq * 64,
                                adesc + (unsigned long long)((s >> 2) * 1024 + (s & 3) * 2),
                                wdesc + (unsigned long long)((s >> 2) * 512 + (s & 3) * 2),
                                idesc, s > 0 ? 1u : 0u);
                }
                asm volatile(
                    "tcgen05.commit.cta_group::1.mbarrier::arrive::one.shared::cluster.b64 [%0];"
                    :: "r"(sCtl + 8) : "memory");
            }
            mbar_wait_parity(sCtl + 8, (unsigned)(cm & 1));
            cm++;
        }
        asm volatile("tcgen05.fence::after_thread_sync;" ::: "memory");

        if (tid < 128) {
            int wsub = tid >> 3, lslot = tid & 7;
            int l = lb * 8 + lslot;
            for (int wq = 0; wq < 8; wq++) {
                unsigned q[64];
                ldtm_x32(q,      tmem + wq * 64);
                ldtm_x32(q + 32, tmem + wq * 64 + 32);
                asm volatile("tcgen05.wait::ld.sync.aligned;" ::: "memory");
                int w = w0 + wq * 16 + wsub;
                if (w < V_ && l < L_) {
                    float* ob = out + ((size_t)n * COUT * V_ + w) * L_ + l;
#pragma unroll
                    for (int o = 0; o < 64; o++) {
                        float val = __uint_as_float(q[o]) + sbo[o];
                        val = val > 0.f ? val : spa * val;
                        ob[(size_t)o * V_ * L_] = val;
                    }
                }
            }
            asm volatile("tcgen05.fence::before_thread_sync;" ::: "memory");
        }
        __syncthreads();
    }
    if (wid == 0)
        asm volatile("tcgen05.dealloc.cta_group::1.sync.aligned.b32 %0, %1;"
                     :: "r"(tmem), "r"(512));
    if (tid == 0)
        asm volatile("mbarrier.inval.shared.b64 [%0];" :: "r"(sCtl + 8) : "memory");
#else
    __syncthreads();
    for (int i = tid; i < 64 * 128 * 94; i += 256) {
        int o = i / (128 * 94);
        int r = i % (128 * 94);
        int wi = r / 94, l = r % 94;
        int w = w0 + wi;
        if (w < V_) {
            float acc = bout[o];
            for (int k = 0; k < 96; k++) {
                int hop = k >> 5, c = k & 31;
                float h;
                if (hop == 0) h = g_xt[((size_t)(n * CIN + c) * LP + l) * VP + w];
                else h = g_x12[((size_t)(((hop - 1) * N_ + n) * CIN + c) * L_ + l) * VP + w];
                acc = fmaf(wout[o * 96 + k], h, acc);
            }
            acc = acc > 0.f ? acc : spa * acc;
            out[(((size_t)n * COUT + o) * V_ + w) * L_ + l] = acc;
        }
    }
#endif
}

// ---------------------------------------------------------------------------
extern "C" void kernel_launch(void* const* d_in, const int* in_sizes, int n_in,
                              void* d_out, int out_size) {
    const float* x    = (const float*)d_in[0];
    const float* A    = (const float*)d_in[1];
    const float* w1   = (const float*)d_in[2];
    const float* b1   = (const float*)d_in[3];
    const float* w2   = (const float*)d_in[4];
    const float* b2   = (const float*)d_in[5];
    const float* w3   = (const float*)d_in[6];
    const float* b3   = (const float*)d_in[7];
    const float* wout = (const float*)d_in[8];
    const float* bout = (const float*)d_in[9];
    const float* pa   = (const float*)d_in[10];
    float* out = (float*)d_out;

    cudaFuncSetAttribute(kernelC,     cudaFuncAttributeMaxDynamicSharedMemorySize, C_SMEM_BYTES);
    cudaFuncSetAttribute(kernelB_mma, cudaFuncAttributeMaxDynamicSharedMemorySize, BM_SMEM);
    cudaFuncSetAttribute(kernelD_mma, cudaFuncAttributeMaxDynamicSharedMemorySize, D_SMEM);
    cudaFuncSetAttribute(kernelX,     cudaFuncAttributeMaxDynamicSharedMemorySize, X_SMEM);

    kernelA<<<dim3(32, 32), dim3(16, 16)>>>(A);
    kernelE<<<24, 256>>>(wout);
    kernelW<<<48, 256>>>(w1, w2, w3);
    kernelX<<<dim3(125, 32), 256, X_SMEM>>>(x);
    kernelB_mma<<<dim3(4, 32), 256, BM_SMEM>>>(b1, b2, b3);
    kernelC<<<dim3(24, 8, 32), 256, C_SMEM_BYTES>>>();
    kernelD_mma<<<dim3(4, 32), 256, D_SMEM>>>(wout, bout, pa, out);
}

// round 6
// speedup vs baseline: 2.9383x; 1.0282x over previous
#include <cuda_runtime.h>
#include <cuda_bf16.h>

#define N_    32
#define CIN   32
#define V_    500
#define T_    96
#define L_    94      // T - K + 1
#define COUT  64
#define VP    512     // padded v/w dim
#define LP    96      // padded l dim in g_xt

// Scratch (zero-initialized at module load; padding regions never written)
__device__ float          g_xt  [N_ * CIN * LP * VP];     // [n][c][l][v] fp32
__device__ __nv_bfloat16  g_xtb [N_ * CIN * LP * VP];     // bf16 copy
__device__ float          g_x12 [2 * N_ * CIN * L_ * VP]; // [mat][n][c][l][w]
__device__ float          g_Apad [VP * VP];               // fallback
__device__ float          g_A2pad[VP * VP];               // fallback
__device__ __nv_bfloat16  g_ATb [VP * VP];                // A^T
__device__ __nv_bfloat16  g_A2Tb[VP * VP];                // (A@A)^T
// xp, pre-swizzled: [n][vc=4][t=96] blocks of 4096 floats; elem (vr,ci) at SW128(vr*128+ci*4)
__device__ float          g_xpsw[N_ * 4 * T_ * 4096];
__device__ float          g_Wcat[128 * 96];               // stacked conv weights (tf32)

#define HAS_TCGEN05 (defined(__CUDA_ARCH_FEAT_SM103_ALL) || defined(__CUDA_ARCH_FEAT_SM100_ALL) || defined(__CUDA_ARCH_FEAT_SM101_ALL))

#define SW128(o) ((o) ^ (((o) >> 3) & 0x70))

static __device__ __forceinline__ unsigned smem_u32(const void* p) {
    unsigned a;
    asm("{ .reg .u64 t; cvta.to.shared.u64 t, %1; cvt.u32.u64 %0, t; }"
        : "=r"(a) : "l"(p));
    return a;
}

static __device__ __forceinline__ float tf32r(float x) {
    float r;
    asm("cvt.rna.tf32.f32 %0, %1;" : "=f"(r) : "f"(x));
    return r;
}

#if HAS_TCGEN05
static __device__ __forceinline__ unsigned elect_one() {
    unsigned p;
    asm volatile("{\n\t.reg .pred p;\n\telect.sync _|p, 0xFFFFFFFF;\n\t"
                 "selp.b32 %0, 1, 0, p;\n\t}" : "=r"(p));
    return p;
}

static __device__ __forceinline__ void mbar_wait_parity(unsigned mbar, unsigned phase) {
    asm volatile(
        "{\n\t.reg .pred P1;\n\t"
        "WL_%=:\n\t"
        "mbarrier.try_wait.parity.acquire.cta.shared::cta.b64 P1, [%0], %1, 0x989680;\n\t"
        "@P1 bra.uni WD_%=;\n\t"
        "bra.uni WL_%=;\n\t"
        "WD_%=:\n\t}"
        :: "r"(mbar), "r"(phase) : "memory");
}

static __device__ __forceinline__ void mma_bf16_ss(unsigned d_tmem, unsigned long long a_desc,
                                                   unsigned long long b_desc, unsigned idesc,
                                                   unsigned en) {
    asm volatile(
        "{\n\t.reg .pred p;\n\t"
        "setp.ne.u32 p, %4, 0;\n\t"
        "tcgen05.mma.cta_group::1.kind::f16 [%0], %1, %2, %3, {%5, %5, %5, %5}, p;\n\t}"
        :: "r"(d_tmem), "l"(a_desc), "l"(b_desc), "r"(idesc), "r"(en), "r"(0u)
        : "memory");
}

static __device__ __forceinline__ void mma_tf32_ss(unsigned d_tmem, unsigned long long a_desc,
                                                   unsigned long long b_desc, unsigned idesc,
                                                   unsigned en) {
    asm volatile(
        "{\n\t.reg .pred p;\n\t"
        "setp.ne.u32 p, %4, 0;\n\t"
        "tcgen05.mma.cta_group::1.kind::tf32 [%0], %1, %2, %3, {%5, %5, %5, %5}, p;\n\t}"
        :: "r"(d_tmem), "l"(a_desc), "l"(b_desc), "r"(idesc), "r"(en), "r"(0u)
        : "memory");
}

static __device__ __forceinline__ void ldtm_x32(unsigned* r, unsigned addr) {
    asm volatile(
        "tcgen05.ld.sync.aligned.32x32b.x32.b32 "
        "{%0, %1, %2, %3, %4, %5, %6, %7, "
        " %8, %9, %10, %11, %12, %13, %14, %15, "
        " %16, %17, %18, %19, %20, %21, %22, %23, "
        " %24, %25, %26, %27, %28, %29, %30, %31}, [%32];"
        : "=r"(r[0]),  "=r"(r[1]),  "=r"(r[2]),  "=r"(r[3]),
          "=r"(r[4]),  "=r"(r[5]),  "=r"(r[6]),  "=r"(r[7]),
          "=r"(r[8]),  "=r"(r[9]),  "=r"(r[10]), "=r"(r[11]),
          "=r"(r[12]), "=r"(r[13]), "=r"(r[14]), "=r"(r[15]),
          "=r"(r[16]), "=r"(r[17]), "=r"(r[18]), "=r"(r[19]),
          "=r"(r[20]), "=r"(r[21]), "=r"(r[22]), "=r"(r[23]),
          "=r"(r[24]), "=r"(r[25]), "=r"(r[26]), "=r"(r[27]),
          "=r"(r[28]), "=r"(r[29]), "=r"(r[30]), "=r"(r[31])
        : "r"(addr));
}

#define DESC_BASE ((2ULL << 61) | (1ULL << 46) | (64ULL << 32) | (1ULL << 16))
#endif  // HAS_TCGEN05

// ---------------------------------------------------------------------------
// Kernel A: A@A; emit fp32 padded (fallback) + bf16 transposed
// ---------------------------------------------------------------------------
__global__ __launch_bounds__(256) void kernelA(const float* __restrict__ A) {
    __shared__ float As[16][16];
    __shared__ float Bs[16][16];
    int tx = threadIdx.x, ty = threadIdx.y;
    int w = blockIdx.x * 16 + tx;
    int v = blockIdx.y * 16 + ty;
    float aval = (v < V_ && w < V_) ? A[v * V_ + w] : 0.f;
    float acc = 0.f;
    for (int u0 = 0; u0 < V_; u0 += 16) {
        int u1 = u0 + tx, u2 = u0 + ty;
        As[ty][tx] = (v < V_ && u1 < V_) ? A[v * V_ + u1] : 0.f;
        Bs[ty][tx] = (u2 < V_ && w < V_) ? A[u2 * V_ + w] : 0.f;
        __syncthreads();
#pragma unroll
        for (int u = 0; u < 16; u++) acc += As[ty][u] * Bs[u][tx];
        __syncthreads();
    }
    float a2val = (v < V_ && w < V_) ? acc : 0.f;
    g_Apad [v * VP + w] = aval;
    g_A2pad[v * VP + w] = a2val;
    g_ATb [w * VP + v] = __float2bfloat16(aval);
    g_A2Tb[w * VP + v] = __float2bfloat16(a2val);
}

// ---------------------------------------------------------------------------
// Kernel W: g_Wcat[row][kk*32+ci]; rows 0-31/32-63/64-95 = conv1/2/3, rest 0
// ---------------------------------------------------------------------------
__global__ __launch_bounds__(256) void kernelW(
    const float* __restrict__ w1, const float* __restrict__ w2,
    const float* __restrict__ w3)
{
    int idx = blockIdx.x * 256 + threadIdx.x;
    if (idx < 128 * 96) {
        int row = idx / 96, kp = idx % 96;
        int kk = kp >> 5, ci = kp & 31;
        float val = 0.f;
        if (row < 32)       val = w1[row * 96 + ci * 3 + kk];
        else if (row < 64)  val = w2[(row - 32) * 96 + ci * 3 + kk];
        else if (row < 96)  val = w3[(row - 64) * 96 + ci * 3 + kk];
        g_Wcat[idx] = tf32r(val);
    }
}

// ---------------------------------------------------------------------------
// Kernel X: x[n][ci][v][t] -> g_xpsw swizzled atom-col blocks (tf32-rounded)
// grid (125, 32), 4 v per block.  Store phase vectorized (STG.128).
// ---------------------------------------------------------------------------
#define X_SMEM (4 * 96 * 33 * 4)
__global__ __launch_bounds__(256) void kernelX(const float* __restrict__ x) {
    extern __shared__ float xs[];          // [vt][33]
    int v0 = blockIdx.x * 4, n = blockIdx.y;
    int tid = threadIdx.x;
    for (int i = tid; i < CIN * 4 * T_; i += 256) {
        int t  = i % T_;
        int r  = i / T_;
        int vi = r & 3;
        int ci = r >> 2;
        xs[(vi * T_ + t) * 33 + ci] = x[((n * CIN + ci) * V_ + v0 + vi) * T_ + t];
    }
    __syncthreads();
    // store: 3072 float4 items: ci4 = i&7, (vi,t) = i>>3
    for (int i = tid; i < 3072; i += 256) {
        int ci4 = i & 7;
        int r   = i >> 3;            // vi*96 + t
        int t   = r % 96;
        int vi  = r / 96;
        const float* s = &xs[r * 33 + ci4 * 4];
        float4 o;
        o.x = tf32r(s[0]); o.y = tf32r(s[1]); o.z = tf32r(s[2]); o.w = tf32r(s[3]);
        int v = v0 + vi, vc = v >> 7, vr = v & 127;
        *(float4*)&g_xpsw[((size_t)(n * 4 + vc) * T_ + t) * 4096
                          + (SW128(vr * 128 + ci4 * 16) >> 2)] = o;
    }
}

// ---------------------------------------------------------------------------
// Kernel B (tcgen05 tf32): per CTA (vc, n, lhalf) — 47/46 l's, t-col ring.
// A = xp (M=128 v), B = Wcat (N=128 conv rows).  grid (4, 64), 256 threads.
// ---------------------------------------------------------------------------
#define BRING 8
#define BM_SMEM (1024 + 49152 + BRING * 16384 + 64)

__global__ __launch_bounds__(256) void kernelB_mma(
    const float* __restrict__ b1, const float* __restrict__ b2,
    const float* __restrict__ b3)
{
    int tid = threadIdx.x, wid = tid >> 5;
    int vc = blockIdx.x;
    int n = blockIdx.y >> 1;
    int lhalf = blockIdx.y & 1;
    int lbase = lhalf * 48;
    int lend  = (lbase + 48 < 94) ? (lbase + 48) : 94;
    int v0 = vc * 128;
    __shared__ float sb[96];
    if (tid < 96) sb[tid] = (tid < 32) ? b1[tid] : (tid < 64) ? b2[tid - 32] : b3[tid - 64];

#if HAS_TCGEN05
    extern __shared__ char smem[];
    unsigned s0 = smem_u32(smem);
    unsigned sW = (s0 + 1023) & ~1023u;
    unsigned sR = sW + 49152;
    unsigned sCtl = sR + BRING * 16384;
    char* pW = smem + (sW - s0);
    char* pR = smem + (sR - s0);

    if (wid == 0) {
        asm volatile("tcgen05.alloc.cta_group::1.sync.aligned.shared::cta.b32 [%0], %1;"
                     :: "r"(sCtl), "r"(512) : "memory");
        asm volatile("tcgen05.relinquish_alloc_permit.cta_group::1.sync.aligned;");
    }
    if (tid == 0)
        asm volatile("mbarrier.init.shared.b64 [%0], %1;" :: "r"(sCtl + 8), "r"(1) : "memory");

    // stage Wcat (B-tile, 128 rows x 96 k, 3 atom-cols)
    for (int i = tid; i < 128 * 24; i += 256) {
        int row = i / 24, kq = (i % 24) * 4;
        unsigned off = (kq >> 5) * 16384 + (row >> 3) * 1024 + SW128((row & 7) * 128 + (kq & 31) * 4);
        *(float4*)(pW + off) = *(const float4*)&g_Wcat[row * 96 + kq];
    }
    asm volatile("fence.proxy.async.shared::cta;" ::: "memory");
    __syncthreads();
    unsigned tmem;
    asm volatile("ld.shared.b32 %0, [%1];" : "=r"(tmem) : "r"(sCtl));

    const unsigned idesc = (1u << 4) | (2u << 7) | (2u << 10) | (16u << 17) | (8u << 24);
    unsigned long long wdesc = DESC_BASE | ((unsigned long long)(sW >> 4) & 0x3FFF);
    unsigned long long rdesc = DESC_BASE | ((unsigned long long)(sR >> 4) & 0x3FFF);

    const float* xbase = g_xpsw + (size_t)(n * 4 + vc) * T_ * 4096;
    int staged = lbase;
    int tcap = (lend + 2 < 96) ? (lend + 2) : 96;

    for (int lb = 0; lb < 12; lb++) {
        int tend = lbase + lb * 4 + 6; if (tend > tcap) tend = tcap;
        for (; staged < tend; staged++) {
            const float4* src = (const float4*)(xbase + (size_t)staged * 4096);
            float4* dst = (float4*)(pR + (staged & (BRING - 1)) * 16384);
            for (int j = tid; j < 1024; j += 256) dst[j] = src[j];
        }
        asm volatile("fence.proxy.async.shared::cta;" ::: "memory");
        __syncthreads();

        if (wid == 0 && elect_one()) {
            asm volatile("tcgen05.fence::after_thread_sync;" ::: "memory");
#pragma unroll
            for (int ls = 0; ls < 4; ls++) {
                int l = lbase + lb * 4 + ls;
                if (l < lend) {
#pragma unroll
                    for (int s = 0; s < 12; s++) {
                        unsigned long long ad = rdesc +
                            (unsigned long long)(((l + (s >> 2)) & (BRING - 1)) * 1024 + (s & 3) * 2);
                        unsigned long long bd = wdesc +
                            (unsigned long long)((s >> 2) * 1024 + (s & 3) * 2);
                        mma_tf32_ss(tmem + ls * 128, ad, bd, idesc, s > 0 ? 1u : 0u);
                    }
                }
            }
            asm volatile(
                "tcgen05.commit.cta_group::1.mbarrier::arrive::one.shared::cluster.b64 [%0];"
                :: "r"(sCtl + 8) : "memory");
        }
        mbar_wait_parity(sCtl + 8, (unsigned)(lb & 1));
        asm volatile("tcgen05.fence::after_thread_sync;" ::: "memory");

        if (tid < 128) {
            int v = v0 + tid;
            for (int ls = 0; ls < 4; ls++) {
                int l = lbase + lb * 4 + ls;
                if (l >= lend) break;
                unsigned q[96];
                ldtm_x32(q,      tmem + ls * 128);
                ldtm_x32(q + 32, tmem + ls * 128 + 32);
                ldtm_x32(q + 64, tmem + ls * 128 + 64);
                asm volatile("tcgen05.wait::ld.sync.aligned;" ::: "memory");
                if (v < V_) {
#pragma unroll
                    for (int c = 0; c < 32; c++) {
                        float t1 = __uint_as_float(q[c])      + sb[c];
                        float t2 = __uint_as_float(q[32 + c]) + sb[32 + c];
                        float t3 = __uint_as_float(q[64 + c]) + sb[64 + c];
                        float r = t1 + 1.f / (1.f + __expf(-t2)) + t3;
                        r = fmaxf(r, 0.f);
                        int idx = ((n * CIN + c) * LP + l) * VP + v;
                        g_xt [idx] = r;
                        g_xtb[idx] = __float2bfloat16(r);
                    }
                }
            }
            asm volatile("tcgen05.fence::before_thread_sync;" ::: "memory");
        }
        __syncthreads();
    }
    if (wid == 0)
        asm volatile("tcgen05.dealloc.cta_group::1.sync.aligned.b32 %0, %1;"
                     :: "r"(tmem), "r"(512));
    if (tid == 0)
        asm volatile("mbarrier.inval.shared.b64 [%0];" :: "r"(sCtl + 8) : "memory");
#else
    __syncthreads();
    for (int i = tid; i < (lend - lbase) * 32 * 128; i += 256) {
        int l = lbase + i / (32 * 128);
        int r = i % (32 * 128);
        int c = r >> 7, vi = r & 127;
        int v = v0 + vi;
        if (v < V_) {
            float a1 = 0.f, a2 = 0.f, a3 = 0.f;
            for (int k = 0; k < 96; k++) {
                int kk = k >> 5, ci = k & 31;
                float xv = g_xpsw[((size_t)(n * 4 + vc) * T_ + l + kk) * 4096
                                  + (SW128(vi * 128 + ci * 4) >> 2)];
                a1 = fmaf(g_Wcat[c * 96 + k], xv, a1);
                a2 = fmaf(g_Wcat[(32 + c) * 96 + k], xv, a2);
                a3 = fmaf(g_Wcat[(64 + c) * 96 + k], xv, a3);
            }
            float r2 = (a1 + sb[c]) + 1.f / (1.f + __expf(-(a2 + sb[32 + c]))) + (a3 + sb[64 + c]);
            r2 = fmaxf(r2, 0.f);
            int idx = ((n * CIN + c) * LP + l) * VP + v;
            g_xt [idx] = r2;
            g_xtb[idx] = __float2bfloat16(r2);
        }
    }
#endif
}

// ---------------------------------------------------------------------------
// Kernel C: diffusion GEMM — bf16 tcgen05, A-tile reused across 2 w-tiles.
// grid (24, 4, 32): x = m-tile, y = mat*2 + whalf, z = n.  256 threads.
// ---------------------------------------------------------------------------
#define C_SMEM_BYTES (80 * 1024)   // real use ~50KB; padded so exactly 2 CTAs/SM (TMEM 256 each)

__global__ __launch_bounds__(256) void kernelC() {
    extern __shared__ char smem[];
    __shared__ int rowbase[128];
    __shared__ int obase[128];

    int tid = threadIdx.x, wid = tid >> 5, lid = tid & 31;
    int m0  = blockIdx.x * 128;
    int mat = blockIdx.y >> 1;
    int wh  = blockIdx.y & 1;
    int n   = blockIdx.z;

    if (tid < 128) {
        int m = m0 + tid;
        bool valid = m < CIN * L_;
        int mm = valid ? m : 0;
        int c = mm / L_, l = mm % L_;
        rowbase[tid] = ((n * CIN + c) * LP + l) * VP;
        obase[tid]   = valid ? ((((mat * N_ + n) * CIN + c) * L_ + l) * VP) : -1;
    }

#if HAS_TCGEN05
    unsigned s0 = smem_u32(smem);
    unsigned sA = (s0 + 1023) & ~1023u;
    unsigned sB0 = sA + 16384;
    unsigned sB1 = sB0 + 16384;
    unsigned sCtl = sB1 + 16384;
    char* pA  = smem + (sA - s0);
    char* pB0 = smem + (sB0 - s0);
    char* pB1 = smem + (sB1 - s0);
    const __nv_bfloat16* __restrict__ Bm = mat ? g_A2Tb : g_ATb;

    if (wid == 0) {
        asm volatile("tcgen05.alloc.cta_group::1.sync.aligned.shared::cta.b32 [%0], %1;"
                     :: "r"(sCtl), "r"(256) : "memory");
        asm volatile("tcgen05.relinquish_alloc_permit.cta_group::1.sync.aligned;");
    }
    if (tid == 0)
        asm volatile("mbarrier.init.shared.b64 [%0], %1;" :: "r"(sCtl + 8), "r"(1) : "memory");
    __syncthreads();
    unsigned tmem;
    asm volatile("ld.shared.b32 %0, [%1];" : "=r"(tmem) : "r"(sCtl));

    const unsigned idesc = 0x490u | (16u << 17) | (8u << 24);
    unsigned long long adesc  = DESC_BASE | ((unsigned long long)(sA  >> 4) & 0x3FFF);
    unsigned long long b0desc = DESC_BASE | ((unsigned long long)(sB0 >> 4) & 0x3FFF);
    unsigned long long b1desc = DESC_BASE | ((unsigned long long)(sB1 >> 4) & 0x3FFF);

    const __nv_bfloat16* pa4[4];
    const __nv_bfloat16* pb0[4];
    const __nv_bfloat16* pb1[4];
    unsigned swo[4];
#pragma unroll
    for (int it = 0; it < 4; it++) {
        int idx = tid + it * 256;
        int row = idx >> 3, c16 = idx & 7;
        swo[it] = SW128((unsigned)(row * 128 + c16 * 16));
        pa4[it] = &g_xtb[rowbase[row] + c16 * 8];
        pb0[it] = &Bm[(wh * 256 + row) * VP + c16 * 8];
        pb1[it] = &Bm[(wh * 256 + 128 + row) * VP + c16 * 8];
    }
    float4 va[4], vb0[4], vb1[4];
#pragma unroll
    for (int it = 0; it < 4; it++) {
        va[it]  = *(const float4*)pa4[it];
        vb0[it] = *(const float4*)pb0[it];
        vb1[it] = *(const float4*)pb1[it];
    }

    for (int kc = 0; kc < 8; kc++) {
#pragma unroll
        for (int it = 0; it < 4; it++) {
            *(float4*)(pA  + swo[it]) = va[it];
            *(float4*)(pB0 + swo[it]) = vb0[it];
            *(float4*)(pB1 + swo[it]) = vb1[it];
        }
        asm volatile("fence.proxy.async.shared::cta;" ::: "memory");
        __syncthreads();
        if (wid == 0 && elect_one()) {
#pragma unroll
            for (int j = 0; j < 4; j++)
                mma_bf16_ss(tmem, adesc + j * 2, b0desc + j * 2, idesc,
                            (kc > 0 || j > 0) ? 1u : 0u);
#pragma unroll
            for (int j = 0; j < 4; j++)
                mma_bf16_ss(tmem + 128, adesc + j * 2, b1desc + j * 2, idesc,
                            (kc > 0 || j > 0) ? 1u : 0u);
            asm volatile(
                "tcgen05.commit.cta_group::1.mbarrier::arrive::one.shared::cluster.b64 [%0];"
                :: "r"(sCtl + 8) : "memory");
        }
        if (kc < 7) {
            int k1 = (kc + 1) * 64;
#pragma unroll
            for (int it = 0; it < 4; it++) {
                va[it]  = *(const float4*)(pa4[it] + k1);
                vb0[it] = *(const float4*)(pb0[it] + k1);
                vb1[it] = *(const float4*)(pb1[it] + k1);
            }
        }
        mbar_wait_parity(sCtl + 8, (unsigned)(kc & 1));
    }

    asm volatile("tcgen05.fence::after_thread_sync;" ::: "memory");

    if (wid < 4) {
        int row = wid * 32 + lid;
        int ob = obase[row];
#pragma unroll
        for (int acc = 0; acc < 2; acc++) {
#pragma unroll
            for (int g = 0; g < 4; g++) {
                unsigned r[32];
                ldtm_x32(r, tmem + acc * 128 + g * 32);
                asm volatile("tcgen05.wait::ld.sync.aligned;" ::: "memory");
                if (ob >= 0) {
#pragma unroll
                    for (int q = 0; q < 8; q++) {
                        float4 o = make_float4(__uint_as_float(r[q * 4 + 0]),
                                               __uint_as_float(r[q * 4 + 1]),
                                               __uint_as_float(r[q * 4 + 2]),
                                               __uint_as_float(r[q * 4 + 3]));
                        *(float4*)&g_x12[ob + wh * 256 + acc * 128 + g * 32 + q * 4] = o;
                    }
                }
            }
        }
    }
    __syncthreads();
    if (tid == 0)
        asm volatile("mbarrier.inval.shared.b64 [%0];" :: "r"(sCtl + 8) : "memory");
    if (wid == 0)
        asm volatile("tcgen05.dealloc.cta_group::1.sync.aligned.b32 %0, %1;"
                     :: "r"(tmem), "r"(256));
#else
    (void)wid; (void)lid;
    float* As = (float*)smem;
    float* Bs = As + 16 * 132;
    const float* __restrict__ Bmf = mat ? g_A2pad : g_Apad;
    __syncthreads();
    int ty = tid >> 4, tx = tid & 15;
    for (int wsel = 0; wsel < 2; wsel++) {
        int w0 = wh * 256 + wsel * 128;
        float acc[8][8] = {};
        for (int k0 = 0; k0 < VP; k0 += 16) {
            __syncthreads();
#pragma unroll
            for (int it = 0; it < 2; it++) {
                int i = tid + it * 256;
                int arow = i >> 2, aq = i & 3;
                float4 va2 = *(const float4*)&g_xt[rowbase[arow] + k0 + aq * 4];
                As[(aq * 4 + 0) * 132 + arow] = va2.x;
                As[(aq * 4 + 1) * 132 + arow] = va2.y;
                As[(aq * 4 + 2) * 132 + arow] = va2.z;
                As[(aq * 4 + 3) * 132 + arow] = va2.w;
                int bk = i >> 5, bw = (i & 31) * 4;
                float4 vb2 = *(const float4*)&Bmf[(k0 + bk) * VP + w0 + bw];
                *(float4*)&Bs[bk * 132 + bw] = vb2;
            }
            __syncthreads();
#pragma unroll
            for (int kk = 0; kk < 16; kk++) {
                float4 a0 = *(const float4*)&As[kk * 132 + ty * 8];
                float4 a1 = *(const float4*)&As[kk * 132 + ty * 8 + 4];
                float4 b0 = *(const float4*)&Bs[kk * 132 + tx * 8];
                float4 b1v = *(const float4*)&Bs[kk * 132 + tx * 8 + 4];
                float ar[8] = {a0.x, a0.y, a0.z, a0.w, a1.x, a1.y, a1.z, a1.w};
                float br[8] = {b0.x, b0.y, b0.z, b0.w, b1v.x, b1v.y, b1v.z, b1v.w};
#pragma unroll
                for (int i = 0; i < 8; i++)
#pragma unroll
                    for (int j = 0; j < 8; j++)
                        acc[i][j] = fmaf(ar[i], br[j], acc[i][j]);
            }
        }
#pragma unroll
        for (int i = 0; i < 8; i++) {
            int ob = obase[ty * 8 + i];
            if (ob >= 0) {
                *(float4*)&g_x12[ob + w0 + tx * 8]     = make_float4(acc[i][0], acc[i][1], acc[i][2], acc[i][3]);
                *(float4*)&g_x12[ob + w0 + tx * 8 + 4] = make_float4(acc[i][4], acc[i][5], acc[i][6], acc[i][7]);
            }
        }
        __syncthreads();
    }
#endif
}

// ---------------------------------------------------------------------------
// Kernel D (tcgen05 tf32): projection + PReLU, double-buffered pipeline.
// Per CTA (wc, n, lhalf): 48 tiles τ = lb*8 + wq; M = 16w x 8l rows, N = 64 o,
// K = 96 (hop,c).  Two A-buffers + two 64-col TMEM quads + two mbarriers.
// grid (4, 64), 256 threads.
// ---------------------------------------------------------------------------
#define D_SMEM (1024 + 24576 + 2 * 49152 + 64)

#if HAS_TCGEN05
static __device__ __forceinline__ void d_stage(
    int tid, int tau, int lbase, int n, int w0, char* pA)
{
    int wq = tau & 7, lb = tau >> 3;
    for (int i = tid; i < 3072; i += 256) {
        int k = i >> 5, lslot = (i >> 2) & 7, wq4 = i & 3;
        int hop = k >> 5, c = k & 31;
        int l = lbase + lb * 8 + lslot;
        int lcl = l > 93 ? 93 : l;
        const float* src;
        if (hop == 0)
            src = g_xt + ((size_t)(n * CIN + c) * LP + lcl) * VP + w0 + wq * 16 + wq4 * 4;
        else
            src = g_x12 + ((size_t)(((hop - 1) * N_ + n) * CIN + c) * L_ + lcl) * VP
                  + w0 + wq * 16 + wq4 * 4;
        float4 v = *(const float4*)src;
        float vv[4] = {tf32r(v.x), tf32r(v.y), tf32r(v.z), tf32r(v.w)};
#pragma unroll
        for (int m = 0; m < 4; m++) {
            int wsub = wq4 * 4 + m;
            unsigned off = hop * 16384 + wsub * 1024 + SW128(lslot * 128 + (k & 31) * 4);
            *(float*)(pA + off) = vv[m];
        }
    }
}

static __device__ __forceinline__ void d_epilogue(
    int tid, int tau, int lbase, int n, int w0, unsigned tmem,
    const float* sbo, float spa, float* out)
{
    if (tid < 128) {
        int wsub = tid >> 3, lslot = tid & 7;
        int wq = tau & 7, lb = tau >> 3;
        int l = lbase + lb * 8 + lslot;
        int w = w0 + wq * 16 + wsub;
        unsigned q[64];
        unsigned base = tmem + (tau & 1) * 64;
        ldtm_x32(q, base);
        ldtm_x32(q + 32, base + 32);
        asm volatile("tcgen05.wait::ld.sync.aligned;" ::: "memory");
        if (w < V_ && l < L_) {
            float* ob = out + ((size_t)n * COUT * V_ + w) * L_ + l;
#pragma unroll
            for (int o = 0; o < 64; o++) {
                float val = __uint_as_float(q[o]) + sbo[o];
                val = val > 0.f ? val : spa * val;
                ob[(size_t)o * V_ * L_] = val;
            }
        }
        asm volatile("tcgen05.fence::before_thread_sync;" ::: "memory");
    }
}
#endif

__global__ __launch_bounds__(256) void kernelD_mma(
    const float* __restrict__ wout,
    const float* __restrict__ bout,
    const float* __restrict__ pa,
    float* __restrict__ out)
{
    int tid = threadIdx.x, wid = tid >> 5;
    int wc = blockIdx.x;
    int n = blockIdx.y >> 1;
    int lhalf = blockIdx.y & 1;
    int lbase = lhalf * 48;
    int w0 = wc * 128;
    __shared__ float sbo[64];
    __shared__ float spa;
    if (tid < 64) sbo[tid] = bout[tid];
    if (tid == 0) spa = pa[0];

#if HAS_TCGEN05
    extern __shared__ char smem[];
    unsigned s0 = smem_u32(smem);
    unsigned sWt = (s0 + 1023) & ~1023u;
    unsigned sA0 = sWt + 24576;
    unsigned sA1 = sA0 + 49152;
    unsigned sCtl = sA1 + 49152;     // [0:4) tmem, [8:16) mbar0, [16:24) mbar1
    char* pWt = smem + (sWt - s0);
    char* pAb[2] = { smem + (sA0 - s0), smem + (sA1 - s0) };

    if (wid == 0) {
        asm volatile("tcgen05.alloc.cta_group::1.sync.aligned.shared::cta.b32 [%0], %1;"
                     :: "r"(sCtl), "r"(128) : "memory");
        asm volatile("tcgen05.relinquish_alloc_permit.cta_group::1.sync.aligned;");
    }
    if (tid == 0) {
        asm volatile("mbarrier.init.shared.b64 [%0], %1;" :: "r"(sCtl + 8), "r"(1) : "memory");
        asm volatile("mbarrier.init.shared.b64 [%0], %1;" :: "r"(sCtl + 16), "r"(1) : "memory");
    }

    // stage w_out (B-tile: 64 rows x 96 k, rows natively K-major)
    for (int i = tid; i < 64 * 24; i += 256) {
        int row = i / 24, kq = (i % 24) * 4;
        unsigned off = (kq >> 5) * 8192 + (row >> 3) * 1024 + SW128((row & 7) * 128 + (kq & 31) * 4);
        float4 v = *(const float4*)&wout[row * 96 + kq];
        v.x = tf32r(v.x); v.y = tf32r(v.y); v.z = tf32r(v.z); v.w = tf32r(v.w);
        *(float4*)(pWt + off) = v;
    }
    asm volatile("fence.proxy.async.shared::cta;" ::: "memory");
    __syncthreads();
    unsigned tmem;
    asm volatile("ld.shared.b32 %0, [%1];" : "=r"(tmem) : "r"(sCtl));

    const unsigned idesc = (1u << 4) | (2u << 7) | (2u << 10) | (8u << 17) | (8u << 24);
    unsigned long long wdesc = DESC_BASE | ((unsigned long long)(sWt >> 4) & 0x3FFF);
    unsigned long long adescb[2] = {
        DESC_BASE | ((unsigned long long)(sA0 >> 4) & 0x3FFF),
        DESC_BASE | ((unsigned long long)(sA1 >> 4) & 0x3FFF)
    };

    // prologue: tile 0
    d_stage(tid, 0, lbase, n, w0, pAb[0]);
    asm volatile("fence.proxy.async.shared::cta;" ::: "memory");
    __syncthreads();
    if (wid == 0 && elect_one()) {
        asm volatile("tcgen05.fence::after_thread_sync;" ::: "memory");
#pragma unroll
        for (int s = 0; s < 12; s++) {
            mma_tf32_ss(tmem,
                        adescb[0] + (unsigned long long)((s >> 2) * 1024 + (s & 3) * 2),
                        wdesc    + (unsigned long long)((s >> 2) * 512 + (s & 3) * 2),
                        idesc, s > 0 ? 1u : 0u);
        }
        asm volatile("tcgen05.commit.cta_group::1.mbarrier::arrive::one.shared::cluster.b64 [%0];"
                     :: "r"(sCtl + 8) : "memory");
    }

    for (int tau = 1; tau < 48; tau++) {
        int b = tau & 1;
        d_stage(tid, tau, lbase, n, w0, pAb[b]);   // overlaps MMA(tau-1)
        asm volatile("fence.proxy.async.shared::cta;" ::: "memory");
        __syncthreads();
        if (wid == 0 && elect_one()) {
            asm volatile("tcgen05.fence::after_thread_sync;" ::: "memory");
#pragma unroll
            for (int s = 0; s < 12; s++) {
                mma_tf32_ss(tmem + b * 64,
                            adescb[b] + (unsigned long long)((s >> 2) * 1024 + (s & 3) * 2),
                            wdesc     + (unsigned long long)((s >> 2) * 512 + (s & 3) * 2),
                            idesc, s > 0 ? 1u : 0u);
            }
            asm volatile("tcgen05.commit.cta_group::1.mbarrier::arrive::one.shared::cluster.b64 [%0];"
                         :: "r"(sCtl + 8 + b * 8) : "memory");
        }
        int tm1 = tau - 1;
        mbar_wait_parity(sCtl + 8 + (tm1 & 1) * 8, (unsigned)((tm1 >> 1) & 1));
        asm volatile("tcgen05.fence::after_thread_sync;" ::: "memory");
        d_epilogue(tid, tm1, lbase, n, w0, tmem, sbo, spa, out);
        __syncthreads();
    }
    mbar_wait_parity(sCtl + 8 + 8, (unsigned)((47 >> 1) & 1));
    asm volatile("tcgen05.fence::after_thread_sync;" ::: "memory");
    d_epilogue(tid, 47, lbase, n, w0, tmem, sbo, spa, out);

    __syncthreads();
    if (wid == 0)
        asm volatile("tcgen05.dealloc.cta_group::1.sync.aligned.b32 %0, %1;"
                     :: "r"(tmem), "r"(128));
    if (tid == 0) {
        asm volatile("mbarrier.inval.shared.b64 [%0];" :: "r"(sCtl + 8) : "memory");
        asm volatile("mbarrier.inval.shared.b64 [%0];" :: "r"(sCtl + 16) : "memory");
    }
#else
    __syncthreads();
    int lend = (lbase + 48 < 94) ? (lbase + 48) : 94;
    int nl = lend - lbase;
    for (int i = tid; i < 64 * 128 * nl; i += 256) {
        int o = i / (128 * nl);
        int r = i % (128 * nl);
        int wi = r / nl, l = lbase + r % nl;
        int w = w0 + wi;
        if (w < V_) {
            float acc = bout[o];
            for (int k = 0; k < 96; k++) {
                int hop = k >> 5, c = k & 31;
                float h;
                if (hop == 0) h = g_xt[((size_t)(n * CIN + c) * LP + l) * VP + w];
                else h = g_x12[((size_t)(((hop - 1) * N_ + n) * CIN + c) * L_ + l) * VP + w];
                acc = fmaf(wout[o * 96 + k], h, acc);
            }
            acc = acc > 0.f ? acc : spa * acc;
            out[(((size_t)n * COUT + o) * V_ + w) * L_ + l] = acc;
        }
    }
#endif
}

// ---------------------------------------------------------------------------
extern "C" void kernel_launch(void* const* d_in, const int* in_sizes, int n_in,
                              void* d_out, int out_size) {
    const float* x    = (const float*)d_in[0];
    const float* A    = (const float*)d_in[1];
    const float* w1   = (const float*)d_in[2];
    const float* b1   = (const float*)d_in[3];
    const float* w2   = (const float*)d_in[4];
    const float* b2   = (const float*)d_in[5];
    const float* w3   = (const float*)d_in[6];
    const float* b3   = (const float*)d_in[7];
    const float* wout = (const float*)d_in[8];
    const float* bout = (const float*)d_in[9];
    const float* pa   = (const float*)d_in[10];
    float* out = (float*)d_out;

    cudaFuncSetAttribute(kernelC,     cudaFuncAttributeMaxDynamicSharedMemorySize, C_SMEM_BYTES);
    cudaFuncSetAttribute(kernelB_mma, cudaFuncAttributeMaxDynamicSharedMemorySize, BM_SMEM);
    cudaFuncSetAttribute(kernelD_mma, cudaFuncAttributeMaxDynamicSharedMemorySize, D_SMEM);
    cudaFuncSetAttribute(kernelX,     cudaFuncAttributeMaxDynamicSharedMemorySize, X_SMEM);

    kernelA<<<dim3(32, 32), dim3(16, 16)>>>(A);
    kernelW<<<48, 256>>>(w1, w2, w3);
    kernelX<<<dim3(125, 32), 256, X_SMEM>>>(x);
    kernelB_mma<<<dim3(4, 64), 256, BM_SMEM>>>(b1, b2, b3);
    kernelC<<<dim3(24, 4, 32), 256, C_SMEM_BYTES>>>();
    kernelD_mma<<<dim3(4, 64), 256, D_SMEM>>>(wout, bout, pa, out);
}